// round 11
// baseline (speedup 1.0000x reference)
#include <cuda_runtime.h>
#include <cuda_bf16.h>
#include <cuda_fp16.h>
#include <math.h>
#include <stdint.h>

#define N_NODES 10000
#define N_EDGES 640000
#define NHID    128
#define EHID    128
#define CSIZE   128

// ---------------- scratch (device globals; no allocation) ----------------
__device__ float g_h_v[N_NODES * NHID];
__device__ __half g_h_v16[N_NODES * NHID];
__device__ __half g_nf16[N_NODES * 64];
__device__ float g_hvdot[N_NODES];
__device__ __half g_h_e16[(size_t)N_EDGES * EHID];  // CSR-ordered rows, fp16 (164MB)
__device__ float g_logit[N_EDGES];                  // CSR-ordered
__device__ __half g_A16[N_NODES * EHID];
__device__ __half g_cv16[N_NODES * CSIZE];
__device__ int   g_cnt[N_NODES];
__device__ int   g_off[N_NODES + 1];
__device__ int   g_cur[N_NODES];
// fragment images: [ng(2)][k8(8)][q(4)][lane(32)] uint4 each (2048 entries / 128x128 matrix)
__device__ uint4 g_BfragE[2048];        // W_edge^T
__device__ uint4 g_WihFrag[3 * 2048];   // W_ih rows (B[n][k] = Wih[n][k])
__device__ uint4 g_WhhFrag[3 * 2048];
__device__ uint4 g_WmsgFrag[2048];      // W_msg^T

#define A_STRIDE 136   // halves; 272 bytes

__device__ __forceinline__ float leaky01(float v) { return v > 0.f ? v : 0.01f * v; }

__device__ __forceinline__ uint32_t smem_u32(const void* p) {
    uint32_t a;
    asm("{ .reg .u64 t; cvta.to.shared.u64 t, %1; cvt.u32.u64 %0, t; }" : "=r"(a) : "l"(p));
    return a;
}
__device__ __forceinline__ void ldsm_x4(uint32_t* r, uint32_t addr) {
    asm volatile("ldmatrix.sync.aligned.m8n8.x4.shared.b16 {%0,%1,%2,%3}, [%4];"
        : "=r"(r[0]), "=r"(r[1]), "=r"(r[2]), "=r"(r[3]) : "r"(addr));
}
__device__ __forceinline__ void mma_f16(float* c, const uint32_t* a, const uint32_t* b) {
    asm volatile("mma.sync.aligned.m16n8k16.row.col.f32.f16.f16.f32 "
        "{%0,%1,%2,%3}, {%4,%5,%6,%7}, {%8,%9}, {%0,%1,%2,%3};"
        : "+f"(c[0]), "+f"(c[1]), "+f"(c[2]), "+f"(c[3])
        : "r"(a[0]), "r"(a[1]), "r"(a[2]), "r"(a[3]), "r"(b[0]), "r"(b[1]));
}

// fragment builders for mma m16n8k16 .col B fragments
__device__ __forceinline__ uint4 frag_colmajor(const float* M, int f) {  // B[n][k] = M[k*128+n]
    int lane = f & 31, q = (f >> 5) & 3, k8 = (f >> 7) & 7, ng = f >> 10;
    int n1 = ng * 64 + q * 16 + (lane >> 2), n2 = n1 + 8;
    int k0 = k8 * 16 + 2 * (lane & 3);
    uint4 v; __half2 h;
    h = __floats2half2_rn(M[k0 * 128 + n1], M[(k0 + 1) * 128 + n1]); v.x = *(uint32_t*)&h;
    h = __floats2half2_rn(M[(k0 + 8) * 128 + n1], M[(k0 + 9) * 128 + n1]); v.y = *(uint32_t*)&h;
    h = __floats2half2_rn(M[k0 * 128 + n2], M[(k0 + 1) * 128 + n2]); v.z = *(uint32_t*)&h;
    h = __floats2half2_rn(M[(k0 + 8) * 128 + n2], M[(k0 + 9) * 128 + n2]); v.w = *(uint32_t*)&h;
    return v;
}
__device__ __forceinline__ uint4 frag_rowmajor(const float* M, int f, int nbase) { // B[n][k] = M[(nbase+n)*128+k]
    int lane = f & 31, q = (f >> 5) & 3, k8 = (f >> 7) & 7, ng = f >> 10;
    int n1 = nbase + ng * 64 + q * 16 + (lane >> 2), n2 = n1 + 8;
    int k0 = k8 * 16 + 2 * (lane & 3);
    uint4 v; __half2 h;
    h = __floats2half2_rn(M[n1 * 128 + k0], M[n1 * 128 + k0 + 1]); v.x = *(uint32_t*)&h;
    h = __floats2half2_rn(M[n1 * 128 + k0 + 8], M[n1 * 128 + k0 + 9]); v.y = *(uint32_t*)&h;
    h = __floats2half2_rn(M[n2 * 128 + k0], M[n2 * 128 + k0 + 1]); v.z = *(uint32_t*)&h;
    h = __floats2half2_rn(M[n2 * 128 + k0 + 8], M[n2 * 128 + k0 + 9]); v.w = *(uint32_t*)&h;
    return v;
}

// ---------------- launch #1: histogram + nf16 + all fragment-image prep ----------------
__global__ void hist_prep_kernel(const int* __restrict__ dst,
                                 const float* __restrict__ nf,
                                 const float* __restrict__ We,
                                 const float* __restrict__ Wih,
                                 const float* __restrict__ Whh,
                                 const float* __restrict__ Wmsg)
{
    int e = blockIdx.x * blockDim.x + threadIdx.x;
    if (e < N_EDGES) atomicAdd(&g_cnt[dst[e]], 1);
    if (e < N_NODES * 32) {
        float2 f = *(const float2*)&nf[e * 2];
        *(__half2*)&g_nf16[e * 2] = __floats2half2_rn(f.x, f.y);
    }
    if (e < 2048) {
        g_BfragE[e] = frag_colmajor(We, e);
    } else if (e < 2048 + 3 * 2048) {
        int idx = e - 2048;
        g_WihFrag[idx] = frag_rowmajor(Wih, idx & 2047, (idx >> 11) * 128);
    } else if (e < 2048 + 6 * 2048) {
        int idx = e - 2048 - 3 * 2048;
        g_WhhFrag[idx] = frag_rowmajor(Whh, idx & 2047, (idx >> 11) * 128);
    } else if (e < 2048 + 7 * 2048) {
        int idx = e - 2048 - 6 * 2048;
        g_WmsgFrag[idx] = frag_colmajor(Wmsg, idx);
    }
}

// ---------------- launch #2: exclusive scan (warp-shuffle) ----------------
__global__ void scan_kernel() {
    __shared__ int warpsum[32];
    __shared__ int s_carry;
    int t = threadIdx.x, lane = t & 31, w = t >> 5;
    if (t == 0) s_carry = 0;
    __syncthreads();
    for (int base = 0; base < N_NODES; base += 1024) {
        int i = base + t;
        int v = (i < N_NODES) ? g_cnt[i] : 0;
        int x = v;
#pragma unroll
        for (int d = 1; d < 32; d <<= 1) {
            int y = __shfl_up_sync(0xffffffffu, x, d);
            if (lane >= d) x += y;
        }
        if (lane == 31) warpsum[w] = x;
        __syncthreads();
        if (w == 0) {
            int s = warpsum[lane];
#pragma unroll
            for (int d = 1; d < 32; d <<= 1) {
                int y = __shfl_up_sync(0xffffffffu, s, d);
                if (lane >= d) s += y;
            }
            warpsum[lane] = s;
        }
        __syncthreads();
        int incl = x + (w ? warpsum[w - 1] : 0) + s_carry;
        if (i < N_NODES) { g_off[i] = incl - v; g_cur[i] = incl - v; }
        __syncthreads();
        if (t == 1023) s_carry = incl;
        __syncthreads();
    }
    if (t == 0) g_off[N_NODES] = s_carry;
}

// ---------------- launch #3: node embed GEMM (K=64, leaky) + fused hvdot + fp16 copy ----------------
__global__ __launch_bounds__(256) void node_embed_kernel(
    const float* __restrict__ nf, const float* __restrict__ Wn,
    const float* __restrict__ bn, const float* __restrict__ Wl)
{
    extern __shared__ float sm[];
    float* sW = sm;            // 64*128
    float* sX = sm + 8192;     // 64*64
    float* sB = sm + 12288;    // 128
    float* sWL = sm + 12416;   // 128
    int t = threadIdx.x;
    int r0g = blockIdx.x * 64;
    for (int i = t; i < 64 * 128; i += 256) {
        int k = i >> 7, c = i & 127;
        sW[i] = Wn[k * 128 + c];
    }
    for (int i = t; i < 64 * 64; i += 256) {
        int r = i >> 6, k = i & 63;
        int gr = r0g + r;
        sX[i] = (gr < N_NODES) ? nf[gr * 64 + k] : 0.f;
    }
    if (t < 128) { sB[t] = bn[t]; sWL[t] = Wl[t]; }
    __syncthreads();
    int cx = t & 31, cy = t >> 5;
    int r0 = cy * 8, c0 = cx * 4;
    float acc[8][4] = {};
#pragma unroll 4
    for (int k = 0; k < 64; k++) {
        float4 w = *(const float4*)&sW[k * 128 + c0];
#pragma unroll
        for (int r = 0; r < 8; r++) {
            float x = sX[(r0 + r) * 64 + k];
            acc[r][0] += x * w.x; acc[r][1] += x * w.y;
            acc[r][2] += x * w.z; acc[r][3] += x * w.w;
        }
    }
    float wl0 = sWL[c0], wl1 = sWL[c0 + 1], wl2 = sWL[c0 + 2], wl3 = sWL[c0 + 3];
#pragma unroll
    for (int r = 0; r < 8; r++) {
        int gr = r0g + r0 + r;
        if (gr >= N_NODES) break;
        float v0 = leaky01(acc[r][0] + sB[c0]);
        float v1 = leaky01(acc[r][1] + sB[c0 + 1]);
        float v2 = leaky01(acc[r][2] + sB[c0 + 2]);
        float v3 = leaky01(acc[r][3] + sB[c0 + 3]);
        *(float4*)&g_h_v[(size_t)gr * 128 + c0] = make_float4(v0, v1, v2, v3);
        __half2 p01 = __floats2half2_rn(v0, v1);
        __half2 p23 = __floats2half2_rn(v2, v3);
        *(uint2*)&g_h_v16[(size_t)gr * 128 + c0] = make_uint2(*(uint32_t*)&p01, *(uint32_t*)&p23);
        float p = v0 * wl0 + v1 * wl1 + v2 * wl2 + v3 * wl3;
        for (int o = 16; o; o >>= 1) p += __shfl_xor_sync(0xffffffffu, p, o);
        if (cx == 0) g_hvdot[gr] = p;
    }
}

// ============ launch #4: edge GEMM on HMMA, 64 edges/CTA, staged h_e writeout ============
#define SM_SRC   0
#define SM_PERM  256
#define SM_BIAS  512
#define SM_WL    1024
#define SM_LOG   1536
#define SM_A     2048
#define SM_EDGE_TOTAL (SM_A + 64 * 272)   // 19456 bytes -> 4 CTAs/SM

__global__ __launch_bounds__(128, 4)
void edge_mma_kernel(const __half* __restrict__ nf16, const float* __restrict__ ef,
                     const int* __restrict__ src, const int* __restrict__ dst,
                     const float* __restrict__ b_edge,
                     const float* __restrict__ W_logit, const float* __restrict__ b_logit,
                     float* __restrict__ outEF)
{
    extern __shared__ __align__(16) char smem[];
    uint32_t sb = smem_u32(smem);
    int t = threadIdx.x, lane = t & 31, wid = t >> 5;
    int e0 = blockIdx.x * 64;
    int* sSrc = (int*)(smem + SM_SRC);
    int* sPerm = (int*)(smem + SM_PERM);
    float* sBias = (float*)(smem + SM_BIAS);
    float* sWL = (float*)(smem + SM_WL);
    float* sLog = (float*)(smem + SM_LOG);

    if (t < 64) {
        sSrc[t] = src[e0 + t];
        sPerm[t] = atomicAdd(&g_cur[dst[e0 + t]], 1);
    }
    sBias[t] = b_edge[t];
    sWL[t] = W_logit[128 + t];
    __syncthreads();

    // ef: single read; passthrough copy + fp16 into A tile (concat cols 64..127)
    {
        const float4* efs = (const float4*)(ef + (size_t)e0 * 64);
        float4* efd = outEF ? (float4*)(outEF + (size_t)e0 * 64) : nullptr;
#pragma unroll
        for (int it = 0; it < 8; it++) {
            int i = t + it * 128;
            float4 v = efs[i];
            if (efd) efd[i] = v;
            int row = i >> 4, j = i & 15;
            __half2 h01 = __floats2half2_rn(v.x, v.y);
            __half2 h23 = __floats2half2_rn(v.z, v.w);
            *(uint2*)(smem + SM_A + row * 272 + 128 + j * 8)
                = make_uint2(*(uint32_t*)&h01, *(uint32_t*)&h23);
        }
    }
    // nf gather: fp16 rows straight into A tile (concat cols 0..63)
    {
        int r = t >> 1, hf = t & 1;
        const uint4* xp = (const uint4*)(nf16 + (size_t)sSrc[r] * 64 + hf * 32);
        uint4* xd = (uint4*)(smem + SM_A + r * 272 + hf * 64);
#pragma unroll
        for (int j = 0; j < 4; j++) xd[j] = xp[j];
    }
    __syncthreads();

    // warp tile: 4 warps, M=32 (mg in 0..1), N=64 (ng in 0..1)
    int mg = wid & 1, ng = wid >> 1;
    int m0 = mg * 32, n0 = ng * 64;
    float acc[2][8][4];
#pragma unroll
    for (int i = 0; i < 2; i++)
#pragma unroll
        for (int j = 0; j < 8; j++)
#pragma unroll
            for (int c = 0; c < 4; c++) acc[i][j][c] = 0.f;

    uint32_t aOffL = ((lane & 15) * A_STRIDE + (lane >> 4) * 8) * 2;
    uint32_t Ab = sb + SM_A;
    const uint4* bf = g_BfragE + ng * 1024 + lane;

#pragma unroll
    for (int k8 = 0; k8 < 8; k8++) {
        uint32_t kb = k8 * 32;
        uint4 bq[4];
#pragma unroll
        for (int q = 0; q < 4; q++)
            bq[q] = bf[k8 * 128 + q * 32];
        uint32_t a[2][4];
        ldsm_x4(a[0], Ab + aOffL + (uint32_t)m0 * 272 + kb);
        ldsm_x4(a[1], Ab + aOffL + (uint32_t)(m0 + 16) * 272 + kb);
#pragma unroll
        for (int ms = 0; ms < 2; ms++)
#pragma unroll
            for (int q = 0; q < 4; q++) {
                const uint32_t* bb = (const uint32_t*)&bq[q];
                mma_f16(acc[ms][q * 2],     a[ms], bb);
                mma_f16(acc[ms][q * 2 + 1], a[ms], bb + 2);
            }
    }
    __syncthreads();   // A tile reads done -> safe to reuse as h_e staging

    // epilogue: bias + leaky -> smem staging (272B-stride rows) + partial logit
#pragma unroll
    for (int ms = 0; ms < 2; ms++) {
        int r1 = m0 + ms * 16 + (lane >> 2);
        int r2 = r1 + 8;
        float lg1 = 0.f, lg2 = 0.f;
#pragma unroll
        for (int ns = 0; ns < 8; ns++) {
            int col = n0 + ns * 8 + (lane & 3) * 2;
            float v0 = leaky01(acc[ms][ns][0] + sBias[col]);
            float v1 = leaky01(acc[ms][ns][1] + sBias[col + 1]);
            float v2 = leaky01(acc[ms][ns][2] + sBias[col]);
            float v3 = leaky01(acc[ms][ns][3] + sBias[col + 1]);
            lg1 += v0 * sWL[col] + v1 * sWL[col + 1];
            lg2 += v2 * sWL[col] + v3 * sWL[col + 1];
            *(__half2*)(smem + SM_A + r1 * 272 + col * 2) = __floats2half2_rn(v0, v1);
            *(__half2*)(smem + SM_A + r2 * 272 + col * 2) = __floats2half2_rn(v2, v3);
        }
        lg1 += __shfl_xor_sync(0xffffffffu, lg1, 1);
        lg1 += __shfl_xor_sync(0xffffffffu, lg1, 2);
        lg2 += __shfl_xor_sync(0xffffffffu, lg2, 1);
        lg2 += __shfl_xor_sync(0xffffffffu, lg2, 2);
        if ((lane & 3) == 0) {
            sLog[r1 * 2 + ng] = lg1;
            sLog[r2 * 2 + ng] = lg2;
        }
    }
    __syncthreads();

    // coalesced h_e writeout: 2 threads/row, 128B each
    {
        int r = t >> 1, hf = t & 1;
        const uint4* sp = (const uint4*)(smem + SM_A + r * 272 + hf * 128);
        uint4* dp = (uint4*)(g_h_e16 + (size_t)sPerm[r] * 128 + hf * 64);
#pragma unroll
        for (int j = 0; j < 8; j++) dp[j] = sp[j];
    }
    if (t < 64) {
        float s = sLog[t * 2] + sLog[t * 2 + 1] + g_hvdot[sSrc[t]] + b_logit[0];
        g_logit[sPerm[t]] = leaky01(s);
    }
}

// ---------------- launch #5: per-node softmax + weighted sum -> A (fp16) ----------------
__global__ void aggregate_kernel() {
    int v = (blockIdx.x * blockDim.x + threadIdx.x) >> 5;
    int lane = threadIdx.x & 31;
    if (v >= N_NODES) return;
    int s = g_off[v], e = g_off[v + 1];
    float mx = -1e30f;
    for (int i = s + lane; i < e; i += 32)
        mx = fmaxf(mx, g_logit[i]);
    for (int o = 16; o; o >>= 1)
        mx = fmaxf(mx, __shfl_xor_sync(0xffffffffu, mx, o));
    float4 acc = make_float4(0.f, 0.f, 0.f, 0.f);
    float den = 0.f;
    for (int i = s; i < e; i++) {
        float w = expf(g_logit[i] - mx);
        den += w;
        uint2 raw = *(const uint2*)(g_h_e16 + (size_t)i * 128 + lane * 4);
        float2 f01 = __half22float2(*(__half2*)&raw.x);
        float2 f23 = __half22float2(*(__half2*)&raw.y);
        acc.x += w * f01.x; acc.y += w * f01.y;
        acc.z += w * f23.x; acc.w += w * f23.y;
    }
    float inv = (e > s) ? 1.f / den : 0.f;
    __half2 p01 = __floats2half2_rn(acc.x * inv, acc.y * inv);
    __half2 p23 = __floats2half2_rn(acc.z * inv, acc.w * inv);
    *(uint2*)&g_A16[v * 128 + lane * 4] = make_uint2(*(uint32_t*)&p01, *(uint32_t*)&p23);
}

// ============ launch #6: C_v = elu(A @ W_msg + b_msg), HMMA fp16 out ============
#define SM16_BIAS 0
#define SM16_X    512
#define SM16_TOTAL (SM16_X + 64 * 272)   // 17920 bytes

__global__ __launch_bounds__(128, 4) void cv16_kernel(const float* __restrict__ b_msg) {
    extern __shared__ __align__(16) char smem[];
    uint32_t sb = smem_u32(smem);
    int t = threadIdx.x, lane = t & 31, wid = t >> 5;
    int e0 = blockIdx.x * 64;
    float* sBias = (float*)(smem + SM16_BIAS);
    sBias[t] = b_msg[t];
    {
        int row = t >> 1, hf = t & 1;
        int gr = e0 + row;
        uint4* xd = (uint4*)(smem + SM16_X + row * 272 + hf * 128);
        if (gr < N_NODES) {
            const uint4* xp = (const uint4*)(g_A16 + (size_t)gr * 128 + hf * 64);
#pragma unroll
            for (int j = 0; j < 8; j++) xd[j] = xp[j];
        } else {
#pragma unroll
            for (int j = 0; j < 8; j++) xd[j] = make_uint4(0, 0, 0, 0);
        }
    }
    __syncthreads();
    int mg = wid & 1, ng = wid >> 1;
    int m0 = mg * 32, n0 = ng * 64;
    float acc[2][8][4];
#pragma unroll
    for (int i = 0; i < 2; i++)
#pragma unroll
        for (int j = 0; j < 8; j++)
#pragma unroll
            for (int c = 0; c < 4; c++) acc[i][j][c] = 0.f;
    uint32_t aOffL = ((lane & 15) * A_STRIDE + (lane >> 4) * 8) * 2;
    uint32_t Ab = sb + SM16_X;
    const uint4* bf = g_WmsgFrag + ng * 1024 + lane;
#pragma unroll
    for (int k8 = 0; k8 < 8; k8++) {
        uint32_t kb = k8 * 32;
        uint4 bq[4];
#pragma unroll
        for (int q = 0; q < 4; q++) bq[q] = bf[k8 * 128 + q * 32];
        uint32_t a[2][4];
        ldsm_x4(a[0], Ab + aOffL + (uint32_t)m0 * 272 + kb);
        ldsm_x4(a[1], Ab + aOffL + (uint32_t)(m0 + 16) * 272 + kb);
#pragma unroll
        for (int ms = 0; ms < 2; ms++)
#pragma unroll
            for (int q = 0; q < 4; q++) {
                const uint32_t* bb = (const uint32_t*)&bq[q];
                mma_f16(acc[ms][q * 2],     a[ms], bb);
                mma_f16(acc[ms][q * 2 + 1], a[ms], bb + 2);
            }
    }
#pragma unroll
    for (int ms = 0; ms < 2; ms++) {
        int r1 = m0 + ms * 16 + (lane >> 2);
#pragma unroll
        for (int rr = 0; rr < 2; rr++) {
            int gr = e0 + r1 + rr * 8;
            if (gr >= N_NODES) continue;
#pragma unroll
            for (int ns = 0; ns < 8; ns++) {
                int col = n0 + ns * 8 + (lane & 3) * 2;
                float v0 = acc[ms][ns][rr * 2]     + sBias[col];
                float v1 = acc[ms][ns][rr * 2 + 1] + sBias[col + 1];
                v0 = (v0 > 0.f) ? v0 : (expf(v0) - 1.f);
                v1 = (v1 > 0.f) ? v1 : (expf(v1) - 1.f);
                *(__half2*)(g_cv16 + (size_t)gr * 128 + col) = __floats2half2_rn(v0, v1);
            }
        }
    }
}

// ============ launch #7: fused GRU: gi+gh GEMMs + gates -> h_new ============
#define SMF_BIH 0
#define SMF_BHH 1536
#define SMF_CV  3072
#define SMF_HV  (SMF_CV + 17408)
#define SMF_TOTAL (SMF_HV + 17408)   // 37888 bytes

// N=32 sub-tile GEMM: acc[ms 2][ns 4][c 4]; bf pre-offset for this (ng, pass)
__device__ __forceinline__ void gemm32(uint32_t Ab, uint32_t aOffL, int m0,
                                       const uint4* __restrict__ bf, float acc[2][4][4])
{
#pragma unroll
    for (int i = 0; i < 2; i++)
#pragma unroll
        for (int j = 0; j < 4; j++)
#pragma unroll
            for (int c = 0; c < 4; c++) acc[i][j][c] = 0.f;
#pragma unroll
    for (int k8 = 0; k8 < 8; k8++) {
        uint32_t kb = k8 * 32;
        uint4 b0 = bf[k8 * 128];
        uint4 b1 = bf[k8 * 128 + 32];
        uint32_t a[2][4];
        ldsm_x4(a[0], Ab + aOffL + (uint32_t)m0 * 272 + kb);
        ldsm_x4(a[1], Ab + aOffL + (uint32_t)(m0 + 16) * 272 + kb);
#pragma unroll
        for (int ms = 0; ms < 2; ms++) {
            const uint32_t* p0 = (const uint32_t*)&b0;
            const uint32_t* p1 = (const uint32_t*)&b1;
            mma_f16(acc[ms][0], a[ms], p0);
            mma_f16(acc[ms][1], a[ms], p0 + 2);
            mma_f16(acc[ms][2], a[ms], p1);
            mma_f16(acc[ms][3], a[ms], p1 + 2);
        }
    }
}

__global__ __launch_bounds__(128) void gru_fused_kernel(
    const float* __restrict__ b_ih, const float* __restrict__ b_hh,
    float* __restrict__ out)
{
    extern __shared__ __align__(16) char smem[];
    uint32_t sb = smem_u32(smem);
    int t = threadIdx.x, lane = t & 31, wid = t >> 5;
    int e0 = blockIdx.x * 64;
    float* sBih = (float*)(smem + SMF_BIH);
    float* sBhh = (float*)(smem + SMF_BHH);
    for (int i = t; i < 384; i += 128) { sBih[i] = b_ih[i]; sBhh[i] = b_hh[i]; }
    {
        int row = t >> 1, hf = t & 1;
        int gr = e0 + row;
        uint4* cd = (uint4*)(smem + SMF_CV + row * 272 + hf * 128);
        uint4* hd = (uint4*)(smem + SMF_HV + row * 272 + hf * 128);
        if (gr < N_NODES) {
            const uint4* cp = (const uint4*)(g_cv16 + (size_t)gr * 128 + hf * 64);
            const uint4* hp = (const uint4*)(g_h_v16 + (size_t)gr * 128 + hf * 64);
#pragma unroll
            for (int j = 0; j < 8; j++) { cd[j] = cp[j]; hd[j] = hp[j]; }
        } else {
#pragma unroll
            for (int j = 0; j < 8; j++) { cd[j] = make_uint4(0,0,0,0); hd[j] = make_uint4(0,0,0,0); }
        }
    }
    __syncthreads();

    int mg = wid & 1, ng = wid >> 1;
    int m0 = mg * 32;
    uint32_t aOffL = ((lane & 15) * A_STRIDE + (lane >> 4) * 8) * 2;
    uint32_t Acv = sb + SMF_CV, Ahv = sb + SMF_HV;

#pragma unroll
    for (int p = 0; p < 2; p++) {
        int c0 = ng * 64 + p * 32;                 // col within each 128-col gate block
        int fbase = ng * 1024 + (2 * p) * 32 + lane;
        float rg[2][4][4], zg[2][4][4], A1[2][4][4], A2[2][4][4];

        // r gate
        gemm32(Acv, aOffL, m0, g_WihFrag + 0 * 2048 + fbase, A1);
        gemm32(Ahv, aOffL, m0, g_WhhFrag + 0 * 2048 + fbase, A2);
#pragma unroll
        for (int ms = 0; ms < 2; ms++)
#pragma unroll
            for (int ns = 0; ns < 4; ns++)
#pragma unroll
                for (int c = 0; c < 4; c++) {
                    int col = c0 + ns * 8 + (lane & 3) * 2 + (c & 1);
                    float v = A1[ms][ns][c] + A2[ms][ns][c] + sBih[col] + sBhh[col];
                    rg[ms][ns][c] = 1.f / (1.f + expf(-v));
                }
        // z gate
        gemm32(Acv, aOffL, m0, g_WihFrag + 1 * 2048 + fbase, A1);
        gemm32(Ahv, aOffL, m0, g_WhhFrag + 1 * 2048 + fbase, A2);
#pragma unroll
        for (int ms = 0; ms < 2; ms++)
#pragma unroll
            for (int ns = 0; ns < 4; ns++)
#pragma unroll
                for (int c = 0; c < 4; c++) {
                    int col = c0 + ns * 8 + (lane & 3) * 2 + (c & 1);
                    float v = A1[ms][ns][c] + A2[ms][ns][c] + sBih[128 + col] + sBhh[128 + col];
                    zg[ms][ns][c] = 1.f / (1.f + expf(-v));
                }
        // n gate + output
        gemm32(Acv, aOffL, m0, g_WihFrag + 2 * 2048 + fbase, A1);
        gemm32(Ahv, aOffL, m0, g_WhhFrag + 2 * 2048 + fbase, A2);
#pragma unroll
        for (int ms = 0; ms < 2; ms++) {
            int r1 = m0 + ms * 16 + (lane >> 2);
#pragma unroll
            for (int rr = 0; rr < 2; rr++) {
                int gr = e0 + r1 + rr * 8;
                if (gr >= N_NODES) continue;
#pragma unroll
                for (int ns = 0; ns < 4; ns++) {
                    int col = c0 + ns * 8 + (lane & 3) * 2;
                    float2 hv = *(const float2*)&g_h_v[(size_t)gr * 128 + col];
                    float h2[2];
#pragma unroll
                    for (int cc = 0; cc < 2; cc++) {
                        int c = rr * 2 + cc;
                        float in_ = A1[ms][ns][c] + sBih[256 + col + cc];
                        float hn_ = A2[ms][ns][c] + sBhh[256 + col + cc];
                        float n_ = tanhf(in_ + rg[ms][ns][c] * hn_);
                        float z_ = zg[ms][ns][c];
                        float hvv = cc ? hv.y : hv.x;
                        float h = (1.f - z_) * n_ + z_ * hvv;
                        h2[cc] = h > 0.f ? h : 0.f;
                    }
                    *(float2*)&out[(size_t)gr * 128 + col] = make_float2(h2[0], h2[1]);
                }
            }
        }
    }
}

// ---------------- launch ----------------
extern "C" void kernel_launch(void* const* d_in, const int* in_sizes, int n_in,
                              void* d_out, int out_size) {
    const float* node_feats = (const float*)d_in[0];
    const float* edge_feats = (const float*)d_in[1];
    const float* W_node  = (const float*)d_in[2];
    const float* b_node  = (const float*)d_in[3];
    const float* W_edge  = (const float*)d_in[4];
    const float* b_edge  = (const float*)d_in[5];
    const float* W_logit = (const float*)d_in[6];
    const float* b_logit = (const float*)d_in[7];
    const float* W_msg   = (const float*)d_in[8];
    const float* b_msg   = (const float*)d_in[9];
    const float* W_ih    = (const float*)d_in[10];
    const float* W_hh    = (const float*)d_in[11];
    const float* b_ih    = (const float*)d_in[12];
    const float* b_hh    = (const float*)d_in[13];
    const int*   src     = (const int*)d_in[14];
    const int*   dst     = (const int*)d_in[15];
    float* out = (float*)d_out;

    int* p_cnt;
    __half* p_nf16;
    cudaGetSymbolAddress((void**)&p_cnt, g_cnt);
    cudaGetSymbolAddress((void**)&p_nf16, g_nf16);

    const int SM_NODE = (64 * 128 + 64 * 64 + 256) * 4;
    cudaFuncSetAttribute(edge_mma_kernel, cudaFuncAttributeMaxDynamicSharedMemorySize, SM_EDGE_TOTAL);
    cudaFuncSetAttribute(node_embed_kernel, cudaFuncAttributeMaxDynamicSharedMemorySize, SM_NODE);
    cudaFuncSetAttribute(cv16_kernel, cudaFuncAttributeMaxDynamicSharedMemorySize, SM16_TOTAL);
    cudaFuncSetAttribute(gru_fused_kernel, cudaFuncAttributeMaxDynamicSharedMemorySize, SMF_TOTAL);

    cudaMemsetAsync(p_cnt, 0, N_NODES * sizeof(int));

    // #1 histogram + nf16 + all fragment prep
    hist_prep_kernel<<<(N_EDGES + 255) / 256, 256>>>(dst, node_feats, W_edge, W_ih, W_hh, W_msg);
    // #2 scan (warp-shuffle)
    scan_kernel<<<1, 1024>>>();
    // #3 node embed + fused hvdot + fp16 copy
    int ntiles64 = (N_NODES + 63) / 64;
    node_embed_kernel<<<ntiles64, 256, SM_NODE>>>(node_feats, W_node, b_node, W_logit);
    // #4 edge GEMM on tensor cores (profiled slot)
    float* outEF = (out_size >= N_NODES * NHID + N_EDGES * 64) ? (out + N_NODES * NHID) : nullptr;
    edge_mma_kernel<<<N_EDGES / 64, 128, SM_EDGE_TOTAL>>>(p_nf16, edge_feats, src, dst,
                                                          b_edge, W_logit, b_logit, outEF);
    // #5 softmax-weighted segment sum -> A16
    aggregate_kernel<<<(N_NODES + 7) / 8, 256>>>();
    // #6 C_v (HMMA, fp16 out)
    cv16_kernel<<<ntiles64, 128, SM16_TOTAL>>>(b_msg);
    // #7 fused GRU GEMMs + gates -> h_new
    gru_fused_kernel<<<ntiles64, 128, SMF_TOTAL>>>(b_ih, b_hh, out);
}

// round 12
// speedup vs baseline: 1.0082x; 1.0082x over previous
#include <cuda_runtime.h>
#include <cuda_bf16.h>
#include <cuda_fp16.h>
#include <math.h>
#include <stdint.h>

#define N_NODES 10000
#define N_EDGES 640000
#define NHID    128
#define EHID    128
#define CSIZE   128

// ---------------- scratch (device globals; no allocation) ----------------
__device__ float g_h_v[N_NODES * NHID];
__device__ __half g_h_v16[N_NODES * NHID];
__device__ __half g_nf16[N_NODES * 64];
__device__ float g_hvdot[N_NODES];
__device__ __half g_h_e16[(size_t)N_EDGES * EHID];  // CSR-ordered rows, fp16 (164MB)
__device__ float g_logit[N_EDGES];                  // CSR-ordered
__device__ __half g_A16[N_NODES * EHID];
__device__ __half g_cv16[N_NODES * CSIZE];
__device__ int   g_cnt[N_NODES];
__device__ int   g_off[N_NODES + 1];
__device__ int   g_cur[N_NODES];
// fragment images: [ng(2)][k8(8)][q(4)][lane(32)] uint4 each (2048 entries / 128x128 matrix)
__device__ uint4 g_BfragE[2048];        // W_edge^T
__device__ uint4 g_WihFrag[3 * 2048];   // W_ih rows (B[n][k] = Wih[n][k])
__device__ uint4 g_WhhFrag[3 * 2048];
__device__ uint4 g_WmsgFrag[2048];      // W_msg^T

#define A_STRIDE 136   // halves; 272 bytes

__device__ __forceinline__ float leaky01(float v) { return v > 0.f ? v : 0.01f * v; }

__device__ __forceinline__ uint32_t smem_u32(const void* p) {
    uint32_t a;
    asm("{ .reg .u64 t; cvta.to.shared.u64 t, %1; cvt.u32.u64 %0, t; }" : "=r"(a) : "l"(p));
    return a;
}
__device__ __forceinline__ void ldsm_x4(uint32_t* r, uint32_t addr) {
    asm volatile("ldmatrix.sync.aligned.m8n8.x4.shared.b16 {%0,%1,%2,%3}, [%4];"
        : "=r"(r[0]), "=r"(r[1]), "=r"(r[2]), "=r"(r[3]) : "r"(addr));
}
__device__ __forceinline__ void mma_f16(float* c, const uint32_t* a, const uint32_t* b) {
    asm volatile("mma.sync.aligned.m16n8k16.row.col.f32.f16.f16.f32 "
        "{%0,%1,%2,%3}, {%4,%5,%6,%7}, {%8,%9}, {%0,%1,%2,%3};"
        : "+f"(c[0]), "+f"(c[1]), "+f"(c[2]), "+f"(c[3])
        : "r"(a[0]), "r"(a[1]), "r"(a[2]), "r"(a[3]), "r"(b[0]), "r"(b[1]));
}

// fragment builders for mma m16n8k16 .col B fragments
__device__ __forceinline__ uint4 frag_colmajor(const float* M, int f) {  // B[n][k] = M[k*128+n]
    int lane = f & 31, q = (f >> 5) & 3, k8 = (f >> 7) & 7, ng = f >> 10;
    int n1 = ng * 64 + q * 16 + (lane >> 2), n2 = n1 + 8;
    int k0 = k8 * 16 + 2 * (lane & 3);
    uint4 v; __half2 h;
    h = __floats2half2_rn(M[k0 * 128 + n1], M[(k0 + 1) * 128 + n1]); v.x = *(uint32_t*)&h;
    h = __floats2half2_rn(M[(k0 + 8) * 128 + n1], M[(k0 + 9) * 128 + n1]); v.y = *(uint32_t*)&h;
    h = __floats2half2_rn(M[k0 * 128 + n2], M[(k0 + 1) * 128 + n2]); v.z = *(uint32_t*)&h;
    h = __floats2half2_rn(M[(k0 + 8) * 128 + n2], M[(k0 + 9) * 128 + n2]); v.w = *(uint32_t*)&h;
    return v;
}
__device__ __forceinline__ uint4 frag_rowmajor(const float* M, int f, int nbase) { // B[n][k] = M[(nbase+n)*128+k]
    int lane = f & 31, q = (f >> 5) & 3, k8 = (f >> 7) & 7, ng = f >> 10;
    int n1 = nbase + ng * 64 + q * 16 + (lane >> 2), n2 = n1 + 8;
    int k0 = k8 * 16 + 2 * (lane & 3);
    uint4 v; __half2 h;
    h = __floats2half2_rn(M[n1 * 128 + k0], M[n1 * 128 + k0 + 1]); v.x = *(uint32_t*)&h;
    h = __floats2half2_rn(M[n1 * 128 + k0 + 8], M[n1 * 128 + k0 + 9]); v.y = *(uint32_t*)&h;
    h = __floats2half2_rn(M[n2 * 128 + k0], M[n2 * 128 + k0 + 1]); v.z = *(uint32_t*)&h;
    h = __floats2half2_rn(M[n2 * 128 + k0 + 8], M[n2 * 128 + k0 + 9]); v.w = *(uint32_t*)&h;
    return v;
}

// ---------------- launch #1: histogram + nf16 + all fragment-image prep ----------------
__global__ void hist_prep_kernel(const int* __restrict__ dst,
                                 const float* __restrict__ nf,
                                 const float* __restrict__ We,
                                 const float* __restrict__ Wih,
                                 const float* __restrict__ Whh,
                                 const float* __restrict__ Wmsg)
{
    int e = blockIdx.x * blockDim.x + threadIdx.x;
    if (e < N_EDGES) atomicAdd(&g_cnt[dst[e]], 1);
    if (e < N_NODES * 32) {
        float2 f = *(const float2*)&nf[e * 2];
        *(__half2*)&g_nf16[e * 2] = __floats2half2_rn(f.x, f.y);
    }
    if (e < 2048) {
        g_BfragE[e] = frag_colmajor(We, e);
    } else if (e < 2048 + 3 * 2048) {
        int idx = e - 2048;
        g_WihFrag[idx] = frag_rowmajor(Wih, idx & 2047, (idx >> 11) * 128);
    } else if (e < 2048 + 6 * 2048) {
        int idx = e - 2048 - 3 * 2048;
        g_WhhFrag[idx] = frag_rowmajor(Whh, idx & 2047, (idx >> 11) * 128);
    } else if (e < 2048 + 7 * 2048) {
        int idx = e - 2048 - 6 * 2048;
        g_WmsgFrag[idx] = frag_colmajor(Wmsg, idx);
    }
}

// ---------------- launch #2: exclusive scan (warp-shuffle) ----------------
__global__ void scan_kernel() {
    __shared__ int warpsum[32];
    __shared__ int s_carry;
    int t = threadIdx.x, lane = t & 31, w = t >> 5;
    if (t == 0) s_carry = 0;
    __syncthreads();
    for (int base = 0; base < N_NODES; base += 1024) {
        int i = base + t;
        int v = (i < N_NODES) ? g_cnt[i] : 0;
        int x = v;
#pragma unroll
        for (int d = 1; d < 32; d <<= 1) {
            int y = __shfl_up_sync(0xffffffffu, x, d);
            if (lane >= d) x += y;
        }
        if (lane == 31) warpsum[w] = x;
        __syncthreads();
        if (w == 0) {
            int s = warpsum[lane];
#pragma unroll
            for (int d = 1; d < 32; d <<= 1) {
                int y = __shfl_up_sync(0xffffffffu, s, d);
                if (lane >= d) s += y;
            }
            warpsum[lane] = s;
        }
        __syncthreads();
        int incl = x + (w ? warpsum[w - 1] : 0) + s_carry;
        if (i < N_NODES) { g_off[i] = incl - v; g_cur[i] = incl - v; }
        __syncthreads();
        if (t == 1023) s_carry = incl;
        __syncthreads();
    }
    if (t == 0) g_off[N_NODES] = s_carry;
}

// ---------------- launch #3: node embed GEMM (K=64, leaky) + fused hvdot + fp16 copy ----------------
__global__ __launch_bounds__(256) void node_embed_kernel(
    const float* __restrict__ nf, const float* __restrict__ Wn,
    const float* __restrict__ bn, const float* __restrict__ Wl)
{
    extern __shared__ float sm[];
    float* sW = sm;            // 64*128
    float* sX = sm + 8192;     // 64*64
    float* sB = sm + 12288;    // 128
    float* sWL = sm + 12416;   // 128
    int t = threadIdx.x;
    int r0g = blockIdx.x * 64;
    for (int i = t; i < 64 * 128; i += 256) {
        int k = i >> 7, c = i & 127;
        sW[i] = Wn[k * 128 + c];
    }
    for (int i = t; i < 64 * 64; i += 256) {
        int r = i >> 6, k = i & 63;
        int gr = r0g + r;
        sX[i] = (gr < N_NODES) ? nf[gr * 64 + k] : 0.f;
    }
    if (t < 128) { sB[t] = bn[t]; sWL[t] = Wl[t]; }
    __syncthreads();
    int cx = t & 31, cy = t >> 5;
    int r0 = cy * 8, c0 = cx * 4;
    float acc[8][4] = {};
#pragma unroll 4
    for (int k = 0; k < 64; k++) {
        float4 w = *(const float4*)&sW[k * 128 + c0];
#pragma unroll
        for (int r = 0; r < 8; r++) {
            float x = sX[(r0 + r) * 64 + k];
            acc[r][0] += x * w.x; acc[r][1] += x * w.y;
            acc[r][2] += x * w.z; acc[r][3] += x * w.w;
        }
    }
    float wl0 = sWL[c0], wl1 = sWL[c0 + 1], wl2 = sWL[c0 + 2], wl3 = sWL[c0 + 3];
#pragma unroll
    for (int r = 0; r < 8; r++) {
        int gr = r0g + r0 + r;
        if (gr >= N_NODES) break;
        float v0 = leaky01(acc[r][0] + sB[c0]);
        float v1 = leaky01(acc[r][1] + sB[c0 + 1]);
        float v2 = leaky01(acc[r][2] + sB[c0 + 2]);
        float v3 = leaky01(acc[r][3] + sB[c0 + 3]);
        *(float4*)&g_h_v[(size_t)gr * 128 + c0] = make_float4(v0, v1, v2, v3);
        __half2 p01 = __floats2half2_rn(v0, v1);
        __half2 p23 = __floats2half2_rn(v2, v3);
        *(uint2*)&g_h_v16[(size_t)gr * 128 + c0] = make_uint2(*(uint32_t*)&p01, *(uint32_t*)&p23);
        float p = v0 * wl0 + v1 * wl1 + v2 * wl2 + v3 * wl3;
        for (int o = 16; o; o >>= 1) p += __shfl_xor_sync(0xffffffffu, p, o);
        if (cx == 0) g_hvdot[gr] = p;
    }
}

// ============ launch #4: edge GEMM on HMMA, 64 edges/CTA, staged h_e writeout ============
#define SM_SRC   0
#define SM_PERM  256
#define SM_BIAS  512
#define SM_WL    1024
#define SM_LOG   1536
#define SM_A     2048
#define SM_EDGE_TOTAL (SM_A + 64 * 272)   // 19456 bytes -> 4 CTAs/SM

__global__ __launch_bounds__(128, 4)
void edge_mma_kernel(const __half* __restrict__ nf16, const float* __restrict__ ef,
                     const int* __restrict__ src, const int* __restrict__ dst,
                     const float* __restrict__ b_edge,
                     const float* __restrict__ W_logit, const float* __restrict__ b_logit,
                     float* __restrict__ outEF)
{
    extern __shared__ __align__(16) char smem[];
    uint32_t sb = smem_u32(smem);
    int t = threadIdx.x, lane = t & 31, wid = t >> 5;
    int e0 = blockIdx.x * 64;
    int* sSrc = (int*)(smem + SM_SRC);
    int* sPerm = (int*)(smem + SM_PERM);
    float* sBias = (float*)(smem + SM_BIAS);
    float* sWL = (float*)(smem + SM_WL);
    float* sLog = (float*)(smem + SM_LOG);

    if (t < 64) {
        sSrc[t] = src[e0 + t];
        sPerm[t] = atomicAdd(&g_cur[dst[e0 + t]], 1);
    }
    sBias[t] = b_edge[t];
    sWL[t] = W_logit[128 + t];
    __syncthreads();

    // ef: single read; passthrough copy + fp16 into A tile (concat cols 64..127)
    {
        const float4* efs = (const float4*)(ef + (size_t)e0 * 64);
        float4* efd = outEF ? (float4*)(outEF + (size_t)e0 * 64) : nullptr;
#pragma unroll
        for (int it = 0; it < 8; it++) {
            int i = t + it * 128;
            float4 v = efs[i];
            if (efd) efd[i] = v;
            int row = i >> 4, j = i & 15;
            __half2 h01 = __floats2half2_rn(v.x, v.y);
            __half2 h23 = __floats2half2_rn(v.z, v.w);
            *(uint2*)(smem + SM_A + row * 272 + 128 + j * 8)
                = make_uint2(*(uint32_t*)&h01, *(uint32_t*)&h23);
        }
    }
    // nf gather: fp16 rows straight into A tile (concat cols 0..63)
    {
        int r = t >> 1, hf = t & 1;
        const uint4* xp = (const uint4*)(nf16 + (size_t)sSrc[r] * 64 + hf * 32);
        uint4* xd = (uint4*)(smem + SM_A + r * 272 + hf * 64);
#pragma unroll
        for (int j = 0; j < 4; j++) xd[j] = xp[j];
    }
    __syncthreads();

    // warp tile: 4 warps, M=32 (mg in 0..1), N=64 (ng in 0..1)
    int mg = wid & 1, ng = wid >> 1;
    int m0 = mg * 32, n0 = ng * 64;
    float acc[2][8][4];
#pragma unroll
    for (int i = 0; i < 2; i++)
#pragma unroll
        for (int j = 0; j < 8; j++)
#pragma unroll
            for (int c = 0; c < 4; c++) acc[i][j][c] = 0.f;

    uint32_t aOffL = ((lane & 15) * A_STRIDE + (lane >> 4) * 8) * 2;
    uint32_t Ab = sb + SM_A;
    const uint4* bf = g_BfragE + ng * 1024 + lane;

#pragma unroll
    for (int k8 = 0; k8 < 8; k8++) {
        uint32_t kb = k8 * 32;
        uint4 bq[4];
#pragma unroll
        for (int q = 0; q < 4; q++)
            bq[q] = bf[k8 * 128 + q * 32];
        uint32_t a[2][4];
        ldsm_x4(a[0], Ab + aOffL + (uint32_t)m0 * 272 + kb);
        ldsm_x4(a[1], Ab + aOffL + (uint32_t)(m0 + 16) * 272 + kb);
#pragma unroll
        for (int ms = 0; ms < 2; ms++)
#pragma unroll
            for (int q = 0; q < 4; q++) {
                const uint32_t* bb = (const uint32_t*)&bq[q];
                mma_f16(acc[ms][q * 2],     a[ms], bb);
                mma_f16(acc[ms][q * 2 + 1], a[ms], bb + 2);
            }
    }
    __syncthreads();   // A tile reads done -> safe to reuse as h_e staging

    // epilogue: bias + leaky -> smem staging (272B-stride rows) + partial logit
#pragma unroll
    for (int ms = 0; ms < 2; ms++) {
        int r1 = m0 + ms * 16 + (lane >> 2);
        int r2 = r1 + 8;
        float lg1 = 0.f, lg2 = 0.f;
#pragma unroll
        for (int ns = 0; ns < 8; ns++) {
            int col = n0 + ns * 8 + (lane & 3) * 2;
            float v0 = leaky01(acc[ms][ns][0] + sBias[col]);
            float v1 = leaky01(acc[ms][ns][1] + sBias[col + 1]);
            float v2 = leaky01(acc[ms][ns][2] + sBias[col]);
            float v3 = leaky01(acc[ms][ns][3] + sBias[col + 1]);
            lg1 += v0 * sWL[col] + v1 * sWL[col + 1];
            lg2 += v2 * sWL[col] + v3 * sWL[col + 1];
            *(__half2*)(smem + SM_A + r1 * 272 + col * 2) = __floats2half2_rn(v0, v1);
            *(__half2*)(smem + SM_A + r2 * 272 + col * 2) = __floats2half2_rn(v2, v3);
        }
        lg1 += __shfl_xor_sync(0xffffffffu, lg1, 1);
        lg1 += __shfl_xor_sync(0xffffffffu, lg1, 2);
        lg2 += __shfl_xor_sync(0xffffffffu, lg2, 1);
        lg2 += __shfl_xor_sync(0xffffffffu, lg2, 2);
        if ((lane & 3) == 0) {
            sLog[r1 * 2 + ng] = lg1;
            sLog[r2 * 2 + ng] = lg2;
        }
    }
    __syncthreads();

    // coalesced h_e writeout: 2 threads/row, 128B each
    {
        int r = t >> 1, hf = t & 1;
        const uint4* sp = (const uint4*)(smem + SM_A + r * 272 + hf * 128);
        uint4* dp = (uint4*)(g_h_e16 + (size_t)sPerm[r] * 128 + hf * 64);
#pragma unroll
        for (int j = 0; j < 8; j++) dp[j] = sp[j];
    }
    if (t < 64) {
        float s = sLog[t * 2] + sLog[t * 2 + 1] + g_hvdot[sSrc[t]] + b_logit[0];
        g_logit[sPerm[t]] = leaky01(s);
    }
}

// ---------------- launch #5: per-node softmax + weighted sum -> A (fp16) ----------------
__global__ void aggregate_kernel() {
    int v = (blockIdx.x * blockDim.x + threadIdx.x) >> 5;
    int lane = threadIdx.x & 31;
    if (v >= N_NODES) return;
    int s = g_off[v], e = g_off[v + 1];
    float mx = -1e30f;
    for (int i = s + lane; i < e; i += 32)
        mx = fmaxf(mx, g_logit[i]);
    for (int o = 16; o; o >>= 1)
        mx = fmaxf(mx, __shfl_xor_sync(0xffffffffu, mx, o));
    float4 acc = make_float4(0.f, 0.f, 0.f, 0.f);
    float den = 0.f;
    for (int i = s; i < e; i++) {
        float w = expf(g_logit[i] - mx);
        den += w;
        uint2 raw = *(const uint2*)(g_h_e16 + (size_t)i * 128 + lane * 4);
        float2 f01 = __half22float2(*(__half2*)&raw.x);
        float2 f23 = __half22float2(*(__half2*)&raw.y);
        acc.x += w * f01.x; acc.y += w * f01.y;
        acc.z += w * f23.x; acc.w += w * f23.y;
    }
    float inv = (e > s) ? 1.f / den : 0.f;
    __half2 p01 = __floats2half2_rn(acc.x * inv, acc.y * inv);
    __half2 p23 = __floats2half2_rn(acc.z * inv, acc.w * inv);
    *(uint2*)&g_A16[v * 128 + lane * 4] = make_uint2(*(uint32_t*)&p01, *(uint32_t*)&p23);
}

// ============ launch #6: C_v = elu(A @ W_msg + b_msg), HMMA fp16 out ============
#define SM16_BIAS 0
#define SM16_X    512
#define SM16_TOTAL (SM16_X + 64 * 272)   // 17920 bytes

__global__ __launch_bounds__(128, 4) void cv16_kernel(const float* __restrict__ b_msg) {
    extern __shared__ __align__(16) char smem[];
    uint32_t sb = smem_u32(smem);
    int t = threadIdx.x, lane = t & 31, wid = t >> 5;
    int e0 = blockIdx.x * 64;
    float* sBias = (float*)(smem + SM16_BIAS);
    sBias[t] = b_msg[t];
    {
        int row = t >> 1, hf = t & 1;
        int gr = e0 + row;
        uint4* xd = (uint4*)(smem + SM16_X + row * 272 + hf * 128);
        if (gr < N_NODES) {
            const uint4* xp = (const uint4*)(g_A16 + (size_t)gr * 128 + hf * 64);
#pragma unroll
            for (int j = 0; j < 8; j++) xd[j] = xp[j];
        } else {
#pragma unroll
            for (int j = 0; j < 8; j++) xd[j] = make_uint4(0, 0, 0, 0);
        }
    }
    __syncthreads();
    int mg = wid & 1, ng = wid >> 1;
    int m0 = mg * 32, n0 = ng * 64;
    float acc[2][8][4];
#pragma unroll
    for (int i = 0; i < 2; i++)
#pragma unroll
        for (int j = 0; j < 8; j++)
#pragma unroll
            for (int c = 0; c < 4; c++) acc[i][j][c] = 0.f;
    uint32_t aOffL = ((lane & 15) * A_STRIDE + (lane >> 4) * 8) * 2;
    uint32_t Ab = sb + SM16_X;
    const uint4* bf = g_WmsgFrag + ng * 1024 + lane;
#pragma unroll
    for (int k8 = 0; k8 < 8; k8++) {
        uint32_t kb = k8 * 32;
        uint4 bq[4];
#pragma unroll
        for (int q = 0; q < 4; q++) bq[q] = bf[k8 * 128 + q * 32];
        uint32_t a[2][4];
        ldsm_x4(a[0], Ab + aOffL + (uint32_t)m0 * 272 + kb);
        ldsm_x4(a[1], Ab + aOffL + (uint32_t)(m0 + 16) * 272 + kb);
#pragma unroll
        for (int ms = 0; ms < 2; ms++)
#pragma unroll
            for (int q = 0; q < 4; q++) {
                const uint32_t* bb = (const uint32_t*)&bq[q];
                mma_f16(acc[ms][q * 2],     a[ms], bb);
                mma_f16(acc[ms][q * 2 + 1], a[ms], bb + 2);
            }
    }
#pragma unroll
    for (int ms = 0; ms < 2; ms++) {
        int r1 = m0 + ms * 16 + (lane >> 2);
#pragma unroll
        for (int rr = 0; rr < 2; rr++) {
            int gr = e0 + r1 + rr * 8;
            if (gr >= N_NODES) continue;
#pragma unroll
            for (int ns = 0; ns < 8; ns++) {
                int col = n0 + ns * 8 + (lane & 3) * 2;
                float v0 = acc[ms][ns][rr * 2]     + sBias[col];
                float v1 = acc[ms][ns][rr * 2 + 1] + sBias[col + 1];
                v0 = (v0 > 0.f) ? v0 : (expf(v0) - 1.f);
                v1 = (v1 > 0.f) ? v1 : (expf(v1) - 1.f);
                *(__half2*)(g_cv16 + (size_t)gr * 128 + col) = __floats2half2_rn(v0, v1);
            }
        }
    }
}

// ============ launch #7: fused GRU (8 warps, 1 pass/warp): gi+gh GEMMs + gates -> h_new ============
#define SMF_BIH 0
#define SMF_BHH 1536
#define SMF_CV  3072
#define SMF_HV  (SMF_CV + 17408)
#define SMF_TOTAL (SMF_HV + 17408)   // 37888 bytes

// N=32 sub-tile GEMM: acc[ms 2][ns 4][c 4]; bf pre-offset for this 32-col slice
__device__ __forceinline__ void gemm32(uint32_t Ab, uint32_t aOffL, int m0,
                                       const uint4* __restrict__ bf, float acc[2][4][4])
{
#pragma unroll
    for (int i = 0; i < 2; i++)
#pragma unroll
        for (int j = 0; j < 4; j++)
#pragma unroll
            for (int c = 0; c < 4; c++) acc[i][j][c] = 0.f;
#pragma unroll
    for (int k8 = 0; k8 < 8; k8++) {
        uint32_t kb = k8 * 32;
        uint4 b0 = bf[k8 * 128];
        uint4 b1 = bf[k8 * 128 + 32];
        uint32_t a[2][4];
        ldsm_x4(a[0], Ab + aOffL + (uint32_t)m0 * 272 + kb);
        ldsm_x4(a[1], Ab + aOffL + (uint32_t)(m0 + 16) * 272 + kb);
#pragma unroll
        for (int ms = 0; ms < 2; ms++) {
            const uint32_t* p0 = (const uint32_t*)&b0;
            const uint32_t* p1 = (const uint32_t*)&b1;
            mma_f16(acc[ms][0], a[ms], p0);
            mma_f16(acc[ms][1], a[ms], p0 + 2);
            mma_f16(acc[ms][2], a[ms], p1);
            mma_f16(acc[ms][3], a[ms], p1 + 2);
        }
    }
}

__global__ __launch_bounds__(256) void gru_fused_kernel(
    const float* __restrict__ b_ih, const float* __restrict__ b_hh,
    float* __restrict__ out)
{
    extern __shared__ __align__(16) char smem[];
    uint32_t sb = smem_u32(smem);
    int t = threadIdx.x, lane = t & 31, wid = t >> 5;
    int e0 = blockIdx.x * 64;
    float* sBih = (float*)(smem + SMF_BIH);
    float* sBhh = (float*)(smem + SMF_BHH);
    for (int i = t; i < 384; i += 256) { sBih[i] = b_ih[i]; sBhh[i] = b_hh[i]; }
    {
        int row = t >> 2, q = t & 3;   // 4 threads per row, 64B each
        int gr = e0 + row;
        uint4* cd = (uint4*)(smem + SMF_CV + row * 272 + q * 64);
        uint4* hd = (uint4*)(smem + SMF_HV + row * 272 + q * 64);
        if (gr < N_NODES) {
            const uint4* cp = (const uint4*)(g_cv16 + (size_t)gr * 128 + q * 32);
            const uint4* hp = (const uint4*)(g_h_v16 + (size_t)gr * 128 + q * 32);
#pragma unroll
            for (int j = 0; j < 4; j++) { cd[j] = cp[j]; hd[j] = hp[j]; }
        } else {
#pragma unroll
            for (int j = 0; j < 4; j++) { cd[j] = make_uint4(0,0,0,0); hd[j] = make_uint4(0,0,0,0); }
        }
    }
    __syncthreads();

    // 8 warps: mg = wid&1 (M half), s = wid>>1 (32-col slice 0..3)
    int mg = wid & 1, s = wid >> 1;
    int m0 = mg * 32;
    int c0 = s * 32;
    uint32_t aOffL = ((lane & 15) * A_STRIDE + (lane >> 4) * 8) * 2;
    uint32_t Acv = sb + SMF_CV, Ahv = sb + SMF_HV;
    int fbase = (s >> 1) * 1024 + (s & 1) * 64 + lane;

    float rg[2][4][4], zg[2][4][4], A1[2][4][4], A2[2][4][4];

    // r gate
    gemm32(Acv, aOffL, m0, g_WihFrag + 0 * 2048 + fbase, A1);
    gemm32(Ahv, aOffL, m0, g_WhhFrag + 0 * 2048 + fbase, A2);
#pragma unroll
    for (int ms = 0; ms < 2; ms++)
#pragma unroll
        for (int ns = 0; ns < 4; ns++)
#pragma unroll
            for (int c = 0; c < 4; c++) {
                int col = c0 + ns * 8 + (lane & 3) * 2 + (c & 1);
                float v = A1[ms][ns][c] + A2[ms][ns][c] + sBih[col] + sBhh[col];
                rg[ms][ns][c] = 1.f / (1.f + expf(-v));
            }
    // z gate
    gemm32(Acv, aOffL, m0, g_WihFrag + 1 * 2048 + fbase, A1);
    gemm32(Ahv, aOffL, m0, g_WhhFrag + 1 * 2048 + fbase, A2);
#pragma unroll
    for (int ms = 0; ms < 2; ms++)
#pragma unroll
        for (int ns = 0; ns < 4; ns++)
#pragma unroll
            for (int c = 0; c < 4; c++) {
                int col = c0 + ns * 8 + (lane & 3) * 2 + (c & 1);
                float v = A1[ms][ns][c] + A2[ms][ns][c] + sBih[128 + col] + sBhh[128 + col];
                zg[ms][ns][c] = 1.f / (1.f + expf(-v));
            }
    // n gate + output
    gemm32(Acv, aOffL, m0, g_WihFrag + 2 * 2048 + fbase, A1);
    gemm32(Ahv, aOffL, m0, g_WhhFrag + 2 * 2048 + fbase, A2);
#pragma unroll
    for (int ms = 0; ms < 2; ms++) {
        int r1 = m0 + ms * 16 + (lane >> 2);
#pragma unroll
        for (int rr = 0; rr < 2; rr++) {
            int gr = e0 + r1 + rr * 8;
            if (gr >= N_NODES) continue;
#pragma unroll
            for (int ns = 0; ns < 4; ns++) {
                int col = c0 + ns * 8 + (lane & 3) * 2;
                float2 hv = *(const float2*)&g_h_v[(size_t)gr * 128 + col];
                float h2[2];
#pragma unroll
                for (int cc = 0; cc < 2; cc++) {
                    int c = rr * 2 + cc;
                    float in_ = A1[ms][ns][c] + sBih[256 + col + cc];
                    float hn_ = A2[ms][ns][c] + sBhh[256 + col + cc];
                    float n_ = tanhf(in_ + rg[ms][ns][c] * hn_);
                    float z_ = zg[ms][ns][c];
                    float hvv = cc ? hv.y : hv.x;
                    float h = (1.f - z_) * n_ + z_ * hvv;
                    h2[cc] = h > 0.f ? h : 0.f;
                }
                *(float2*)&out[(size_t)gr * 128 + col] = make_float2(h2[0], h2[1]);
            }
        }
    }
}

// ---------------- launch ----------------
extern "C" void kernel_launch(void* const* d_in, const int* in_sizes, int n_in,
                              void* d_out, int out_size) {
    const float* node_feats = (const float*)d_in[0];
    const float* edge_feats = (const float*)d_in[1];
    const float* W_node  = (const float*)d_in[2];
    const float* b_node  = (const float*)d_in[3];
    const float* W_edge  = (const float*)d_in[4];
    const float* b_edge  = (const float*)d_in[5];
    const float* W_logit = (const float*)d_in[6];
    const float* b_logit = (const float*)d_in[7];
    const float* W_msg   = (const float*)d_in[8];
    const float* b_msg   = (const float*)d_in[9];
    const float* W_ih    = (const float*)d_in[10];
    const float* W_hh    = (const float*)d_in[11];
    const float* b_ih    = (const float*)d_in[12];
    const float* b_hh    = (const float*)d_in[13];
    const int*   src     = (const int*)d_in[14];
    const int*   dst     = (const int*)d_in[15];
    float* out = (float*)d_out;

    int* p_cnt;
    __half* p_nf16;
    cudaGetSymbolAddress((void**)&p_cnt, g_cnt);
    cudaGetSymbolAddress((void**)&p_nf16, g_nf16);

    const int SM_NODE = (64 * 128 + 64 * 64 + 256) * 4;
    cudaFuncSetAttribute(edge_mma_kernel, cudaFuncAttributeMaxDynamicSharedMemorySize, SM_EDGE_TOTAL);
    cudaFuncSetAttribute(node_embed_kernel, cudaFuncAttributeMaxDynamicSharedMemorySize, SM_NODE);
    cudaFuncSetAttribute(cv16_kernel, cudaFuncAttributeMaxDynamicSharedMemorySize, SM16_TOTAL);
    cudaFuncSetAttribute(gru_fused_kernel, cudaFuncAttributeMaxDynamicSharedMemorySize, SMF_TOTAL);

    cudaMemsetAsync(p_cnt, 0, N_NODES * sizeof(int));

    // #1 histogram + nf16 + all fragment prep
    hist_prep_kernel<<<(N_EDGES + 255) / 256, 256>>>(dst, node_feats, W_edge, W_ih, W_hh, W_msg);
    // #2 scan (warp-shuffle)
    scan_kernel<<<1, 1024>>>();
    // #3 node embed + fused hvdot + fp16 copy
    int ntiles64 = (N_NODES + 63) / 64;
    node_embed_kernel<<<ntiles64, 256, SM_NODE>>>(node_feats, W_node, b_node, W_logit);
    // #4 edge GEMM on tensor cores (profiled slot)
    float* outEF = (out_size >= N_NODES * NHID + N_EDGES * 64) ? (out + N_NODES * NHID) : nullptr;
    edge_mma_kernel<<<N_EDGES / 64, 128, SM_EDGE_TOTAL>>>(p_nf16, edge_feats, src, dst,
                                                          b_edge, W_logit, b_logit, outEF);
    // #5 softmax-weighted segment sum -> A16
    aggregate_kernel<<<(N_NODES + 7) / 8, 256>>>();
    // #6 C_v (HMMA, fp16 out)
    cv16_kernel<<<ntiles64, 128, SM16_TOTAL>>>(b_msg);
    // #7 fused GRU (8 warps, single pass) -> h_new
    gru_fused_kernel<<<ntiles64, 256, SMF_TOTAL>>>(b_ih, b_hh, out);
}

// round 13
// speedup vs baseline: 1.0656x; 1.0569x over previous
#include <cuda_runtime.h>
#include <cuda_bf16.h>
#include <cuda_fp16.h>
#include <math.h>
#include <stdint.h>

#define N_NODES 10000
#define N_EDGES 640000
#define NHID    128
#define EHID    128
#define CSIZE   128

// ---------------- scratch (device globals; no allocation) ----------------
__device__ float g_h_v[N_NODES * NHID];
__device__ __half g_h_v16[N_NODES * NHID];
__device__ __half g_nf16[N_NODES * 64];
__device__ float g_hvdot[N_NODES];
__device__ __half g_h_e16[(size_t)N_EDGES * EHID];  // CSR-ordered rows, fp16 (164MB)
__device__ float g_logit[N_EDGES];                  // CSR-ordered
__device__ __half g_A16[N_NODES * EHID];
__device__ __half g_cv16[N_NODES * CSIZE];
__device__ float g_gi[N_NODES * 3 * NHID];
__device__ float g_gh[N_NODES * 3 * NHID];
__device__ int   g_cnt[N_NODES];
__device__ int   g_off[N_NODES + 1];
__device__ int   g_cur[N_NODES];
// fragment images: [ng(2)][k8(8)][q(4)][lane(32)] uint4 each (2048 entries / 128x128 matrix)
__device__ uint4 g_BfragE[2048];        // W_edge^T
__device__ uint4 g_WihFrag[3 * 2048];   // W_ih rows (B[n][k] = Wih[n][k])
__device__ uint4 g_WhhFrag[3 * 2048];
__device__ uint4 g_WmsgFrag[2048];      // W_msg^T

#define A_STRIDE 136   // halves; 272 bytes

__device__ __forceinline__ float leaky01(float v) { return v > 0.f ? v : 0.01f * v; }

__device__ __forceinline__ uint32_t smem_u32(const void* p) {
    uint32_t a;
    asm("{ .reg .u64 t; cvta.to.shared.u64 t, %1; cvt.u32.u64 %0, t; }" : "=r"(a) : "l"(p));
    return a;
}
__device__ __forceinline__ void ldsm_x4(uint32_t* r, uint32_t addr) {
    asm volatile("ldmatrix.sync.aligned.m8n8.x4.shared.b16 {%0,%1,%2,%3}, [%4];"
        : "=r"(r[0]), "=r"(r[1]), "=r"(r[2]), "=r"(r[3]) : "r"(addr));
}
__device__ __forceinline__ void mma_f16(float* c, const uint32_t* a, const uint32_t* b) {
    asm volatile("mma.sync.aligned.m16n8k16.row.col.f32.f16.f16.f32 "
        "{%0,%1,%2,%3}, {%4,%5,%6,%7}, {%8,%9}, {%0,%1,%2,%3};"
        : "+f"(c[0]), "+f"(c[1]), "+f"(c[2]), "+f"(c[3])
        : "r"(a[0]), "r"(a[1]), "r"(a[2]), "r"(a[3]), "r"(b[0]), "r"(b[1]));
}

// fragment builders for mma m16n8k16 .col B fragments
__device__ __forceinline__ uint4 frag_colmajor(const float* M, int f) {  // B[n][k] = M[k*128+n]
    int lane = f & 31, q = (f >> 5) & 3, k8 = (f >> 7) & 7, ng = f >> 10;
    int n1 = ng * 64 + q * 16 + (lane >> 2), n2 = n1 + 8;
    int k0 = k8 * 16 + 2 * (lane & 3);
    uint4 v; __half2 h;
    h = __floats2half2_rn(M[k0 * 128 + n1], M[(k0 + 1) * 128 + n1]); v.x = *(uint32_t*)&h;
    h = __floats2half2_rn(M[(k0 + 8) * 128 + n1], M[(k0 + 9) * 128 + n1]); v.y = *(uint32_t*)&h;
    h = __floats2half2_rn(M[k0 * 128 + n2], M[(k0 + 1) * 128 + n2]); v.z = *(uint32_t*)&h;
    h = __floats2half2_rn(M[(k0 + 8) * 128 + n2], M[(k0 + 9) * 128 + n2]); v.w = *(uint32_t*)&h;
    return v;
}
__device__ __forceinline__ uint4 frag_rowmajor(const float* M, int f, int nbase) { // B[n][k] = M[(nbase+n)*128+k]
    int lane = f & 31, q = (f >> 5) & 3, k8 = (f >> 7) & 7, ng = f >> 10;
    int n1 = nbase + ng * 64 + q * 16 + (lane >> 2), n2 = n1 + 8;
    int k0 = k8 * 16 + 2 * (lane & 3);
    uint4 v; __half2 h;
    h = __floats2half2_rn(M[n1 * 128 + k0], M[n1 * 128 + k0 + 1]); v.x = *(uint32_t*)&h;
    h = __floats2half2_rn(M[n1 * 128 + k0 + 8], M[n1 * 128 + k0 + 9]); v.y = *(uint32_t*)&h;
    h = __floats2half2_rn(M[n2 * 128 + k0], M[n2 * 128 + k0 + 1]); v.z = *(uint32_t*)&h;
    h = __floats2half2_rn(M[n2 * 128 + k0 + 8], M[n2 * 128 + k0 + 9]); v.w = *(uint32_t*)&h;
    return v;
}

// ---------------- launch #1: histogram + nf16 + all fragment-image prep ----------------
__global__ void hist_prep_kernel(const int* __restrict__ dst,
                                 const float* __restrict__ nf,
                                 const float* __restrict__ We,
                                 const float* __restrict__ Wih,
                                 const float* __restrict__ Whh,
                                 const float* __restrict__ Wmsg)
{
    int e = blockIdx.x * blockDim.x + threadIdx.x;
    if (e < N_EDGES) atomicAdd(&g_cnt[dst[e]], 1);
    if (e < N_NODES * 32) {
        float2 f = *(const float2*)&nf[e * 2];
        *(__half2*)&g_nf16[e * 2] = __floats2half2_rn(f.x, f.y);
    }
    if (e < 2048) {
        g_BfragE[e] = frag_colmajor(We, e);
    } else if (e < 2048 + 3 * 2048) {
        int idx = e - 2048;
        g_WihFrag[idx] = frag_rowmajor(Wih, idx & 2047, (idx >> 11) * 128);
    } else if (e < 2048 + 6 * 2048) {
        int idx = e - 2048 - 3 * 2048;
        g_WhhFrag[idx] = frag_rowmajor(Whh, idx & 2047, (idx >> 11) * 128);
    } else if (e < 2048 + 7 * 2048) {
        int idx = e - 2048 - 6 * 2048;
        g_WmsgFrag[idx] = frag_colmajor(Wmsg, idx);
    }
}

// ---------------- launch #2: exclusive scan (warp-shuffle) ----------------
__global__ void scan_kernel() {
    __shared__ int warpsum[32];
    __shared__ int s_carry;
    int t = threadIdx.x, lane = t & 31, w = t >> 5;
    if (t == 0) s_carry = 0;
    __syncthreads();
    for (int base = 0; base < N_NODES; base += 1024) {
        int i = base + t;
        int v = (i < N_NODES) ? g_cnt[i] : 0;
        int x = v;
#pragma unroll
        for (int d = 1; d < 32; d <<= 1) {
            int y = __shfl_up_sync(0xffffffffu, x, d);
            if (lane >= d) x += y;
        }
        if (lane == 31) warpsum[w] = x;
        __syncthreads();
        if (w == 0) {
            int s = warpsum[lane];
#pragma unroll
            for (int d = 1; d < 32; d <<= 1) {
                int y = __shfl_up_sync(0xffffffffu, s, d);
                if (lane >= d) s += y;
            }
            warpsum[lane] = s;
        }
        __syncthreads();
        int incl = x + (w ? warpsum[w - 1] : 0) + s_carry;
        if (i < N_NODES) { g_off[i] = incl - v; g_cur[i] = incl - v; }
        __syncthreads();
        if (t == 1023) s_carry = incl;
        __syncthreads();
    }
    if (t == 0) g_off[N_NODES] = s_carry;
}

// ---------------- launch #3: node embed GEMM (K=64, leaky) + fused hvdot + fp16 copy ----------------
__global__ __launch_bounds__(256) void node_embed_kernel(
    const float* __restrict__ nf, const float* __restrict__ Wn,
    const float* __restrict__ bn, const float* __restrict__ Wl)
{
    extern __shared__ float sm[];
    float* sW = sm;            // 64*128
    float* sX = sm + 8192;     // 64*64
    float* sB = sm + 12288;    // 128
    float* sWL = sm + 12416;   // 128
    int t = threadIdx.x;
    int r0g = blockIdx.x * 64;
    for (int i = t; i < 64 * 128; i += 256) {
        int k = i >> 7, c = i & 127;
        sW[i] = Wn[k * 128 + c];
    }
    for (int i = t; i < 64 * 64; i += 256) {
        int r = i >> 6, k = i & 63;
        int gr = r0g + r;
        sX[i] = (gr < N_NODES) ? nf[gr * 64 + k] : 0.f;
    }
    if (t < 128) { sB[t] = bn[t]; sWL[t] = Wl[t]; }
    __syncthreads();
    int cx = t & 31, cy = t >> 5;
    int r0 = cy * 8, c0 = cx * 4;
    float acc[8][4] = {};
#pragma unroll 4
    for (int k = 0; k < 64; k++) {
        float4 w = *(const float4*)&sW[k * 128 + c0];
#pragma unroll
        for (int r = 0; r < 8; r++) {
            float x = sX[(r0 + r) * 64 + k];
            acc[r][0] += x * w.x; acc[r][1] += x * w.y;
            acc[r][2] += x * w.z; acc[r][3] += x * w.w;
        }
    }
    float wl0 = sWL[c0], wl1 = sWL[c0 + 1], wl2 = sWL[c0 + 2], wl3 = sWL[c0 + 3];
#pragma unroll
    for (int r = 0; r < 8; r++) {
        int gr = r0g + r0 + r;
        if (gr >= N_NODES) break;
        float v0 = leaky01(acc[r][0] + sB[c0]);
        float v1 = leaky01(acc[r][1] + sB[c0 + 1]);
        float v2 = leaky01(acc[r][2] + sB[c0 + 2]);
        float v3 = leaky01(acc[r][3] + sB[c0 + 3]);
        *(float4*)&g_h_v[(size_t)gr * 128 + c0] = make_float4(v0, v1, v2, v3);
        __half2 p01 = __floats2half2_rn(v0, v1);
        __half2 p23 = __floats2half2_rn(v2, v3);
        *(uint2*)&g_h_v16[(size_t)gr * 128 + c0] = make_uint2(*(uint32_t*)&p01, *(uint32_t*)&p23);
        float p = v0 * wl0 + v1 * wl1 + v2 * wl2 + v3 * wl3;
        for (int o = 16; o; o >>= 1) p += __shfl_xor_sync(0xffffffffu, p, o);
        if (cx == 0) g_hvdot[gr] = p;
    }
}

// ============ launch #4: edge GEMM on HMMA, warp tile M=64 x N=32 (B read once/CTA) ============
#define SM_SRC   0
#define SM_PERM  256
#define SM_BIAS  512
#define SM_WL    1024
#define SM_LOG   1536     // 256 floats (64 rows x 4 slices)
#define SM_A     2560
#define SM_EDGE_TOTAL (SM_A + 64 * 272)   // 19968 bytes -> 4 CTAs/SM

__global__ __launch_bounds__(128, 4)
void edge_mma_kernel(const __half* __restrict__ nf16, const float* __restrict__ ef,
                     const int* __restrict__ src, const int* __restrict__ dst,
                     const float* __restrict__ b_edge,
                     const float* __restrict__ W_logit, const float* __restrict__ b_logit,
                     float* __restrict__ outEF)
{
    extern __shared__ __align__(16) char smem[];
    uint32_t sb = smem_u32(smem);
    int t = threadIdx.x, lane = t & 31, wid = t >> 5;
    int e0 = blockIdx.x * 64;
    int* sSrc = (int*)(smem + SM_SRC);
    int* sPerm = (int*)(smem + SM_PERM);
    float* sBias = (float*)(smem + SM_BIAS);
    float* sWL = (float*)(smem + SM_WL);
    float* sLog = (float*)(smem + SM_LOG);

    if (t < 64) {
        sSrc[t] = src[e0 + t];
        sPerm[t] = atomicAdd(&g_cur[dst[e0 + t]], 1);
    }
    sBias[t] = b_edge[t];
    sWL[t] = W_logit[128 + t];
    __syncthreads();

    // ef: single read; passthrough copy + fp16 into A tile (concat cols 64..127)
    {
        const float4* efs = (const float4*)(ef + (size_t)e0 * 64);
        float4* efd = outEF ? (float4*)(outEF + (size_t)e0 * 64) : nullptr;
#pragma unroll
        for (int it = 0; it < 8; it++) {
            int i = t + it * 128;
            float4 v = efs[i];
            if (efd) efd[i] = v;
            int row = i >> 4, j = i & 15;
            __half2 h01 = __floats2half2_rn(v.x, v.y);
            __half2 h23 = __floats2half2_rn(v.z, v.w);
            *(uint2*)(smem + SM_A + row * 272 + 128 + j * 8)
                = make_uint2(*(uint32_t*)&h01, *(uint32_t*)&h23);
        }
    }
    // nf gather: fp16 rows straight into A tile (concat cols 0..63)
    {
        int r = t >> 1, hf = t & 1;
        const uint4* xp = (const uint4*)(nf16 + (size_t)sSrc[r] * 64 + hf * 32);
        uint4* xd = (uint4*)(smem + SM_A + r * 272 + hf * 64);
#pragma unroll
        for (int j = 0; j < 4; j++) xd[j] = xp[j];
    }
    __syncthreads();

    // warp tile: 4 warps, each M=64 (all rows) x N=32 (slice s = wid)
    int s = wid;
    int n0 = s * 32;
    float acc[4][4][4];
#pragma unroll
    for (int i = 0; i < 4; i++)
#pragma unroll
        for (int j = 0; j < 4; j++)
#pragma unroll
            for (int c = 0; c < 4; c++) acc[i][j][c] = 0.f;

    uint32_t aOffL = ((lane & 15) * A_STRIDE + (lane >> 4) * 8) * 2;
    uint32_t Ab = sb + SM_A;
    const uint4* bf = g_BfragE + (s >> 1) * 1024 + lane;
    int qb = (s & 1) * 2;

#pragma unroll
    for (int k8 = 0; k8 < 8; k8++) {
        uint32_t kb = k8 * 32;
        uint4 b0 = bf[k8 * 128 + (qb + 0) * 32];
        uint4 b1 = bf[k8 * 128 + (qb + 1) * 32];
        uint32_t a[4][4];
#pragma unroll
        for (int ms = 0; ms < 4; ms++)
            ldsm_x4(a[ms], Ab + aOffL + (uint32_t)(ms * 16) * 272 + kb);
        const uint32_t* p0 = (const uint32_t*)&b0;
        const uint32_t* p1 = (const uint32_t*)&b1;
#pragma unroll
        for (int ms = 0; ms < 4; ms++) {
            mma_f16(acc[ms][0], a[ms], p0);
            mma_f16(acc[ms][1], a[ms], p0 + 2);
            mma_f16(acc[ms][2], a[ms], p1);
            mma_f16(acc[ms][3], a[ms], p1 + 2);
        }
    }
    __syncthreads();   // A tile reads done -> safe to reuse as h_e staging

    // epilogue: bias + leaky -> smem staging (272B-stride rows) + partial logit
#pragma unroll
    for (int ms = 0; ms < 4; ms++) {
        int r1 = ms * 16 + (lane >> 2);
        int r2 = r1 + 8;
        float lg1 = 0.f, lg2 = 0.f;
#pragma unroll
        for (int ns = 0; ns < 4; ns++) {
            int col = n0 + ns * 8 + (lane & 3) * 2;
            float v0 = leaky01(acc[ms][ns][0] + sBias[col]);
            float v1 = leaky01(acc[ms][ns][1] + sBias[col + 1]);
            float v2 = leaky01(acc[ms][ns][2] + sBias[col]);
            float v3 = leaky01(acc[ms][ns][3] + sBias[col + 1]);
            lg1 += v0 * sWL[col] + v1 * sWL[col + 1];
            lg2 += v2 * sWL[col] + v3 * sWL[col + 1];
            *(__half2*)(smem + SM_A + r1 * 272 + col * 2) = __floats2half2_rn(v0, v1);
            *(__half2*)(smem + SM_A + r2 * 272 + col * 2) = __floats2half2_rn(v2, v3);
        }
        lg1 += __shfl_xor_sync(0xffffffffu, lg1, 1);
        lg1 += __shfl_xor_sync(0xffffffffu, lg1, 2);
        lg2 += __shfl_xor_sync(0xffffffffu, lg2, 1);
        lg2 += __shfl_xor_sync(0xffffffffu, lg2, 2);
        if ((lane & 3) == 0) {
            sLog[r1 * 4 + s] = lg1;
            sLog[r2 * 4 + s] = lg2;
        }
    }
    __syncthreads();

    // coalesced h_e writeout: 2 threads/row, 128B each
    {
        int r = t >> 1, hf = t & 1;
        const uint4* sp = (const uint4*)(smem + SM_A + r * 272 + hf * 128);
        uint4* dp = (uint4*)(g_h_e16 + (size_t)sPerm[r] * 128 + hf * 64);
#pragma unroll
        for (int j = 0; j < 8; j++) dp[j] = sp[j];
    }
    if (t < 64) {
        float sum = sLog[t * 4] + sLog[t * 4 + 1] + sLog[t * 4 + 2] + sLog[t * 4 + 3]
                  + g_hvdot[sSrc[t]] + b_logit[0];
        g_logit[sPerm[t]] = leaky01(sum);
    }
}

// ---------------- launch #5: per-node softmax + weighted sum -> A (fp16) ----------------
__global__ void aggregate_kernel() {
    int v = (blockIdx.x * blockDim.x + threadIdx.x) >> 5;
    int lane = threadIdx.x & 31;
    if (v >= N_NODES) return;
    int s = g_off[v], e = g_off[v + 1];
    float mx = -1e30f;
    for (int i = s + lane; i < e; i += 32)
        mx = fmaxf(mx, g_logit[i]);
    for (int o = 16; o; o >>= 1)
        mx = fmaxf(mx, __shfl_xor_sync(0xffffffffu, mx, o));
    float4 acc = make_float4(0.f, 0.f, 0.f, 0.f);
    float den = 0.f;
    for (int i = s; i < e; i++) {
        float w = expf(g_logit[i] - mx);
        den += w;
        uint2 raw = *(const uint2*)(g_h_e16 + (size_t)i * 128 + lane * 4);
        float2 f01 = __half22float2(*(__half2*)&raw.x);
        float2 f23 = __half22float2(*(__half2*)&raw.y);
        acc.x += w * f01.x; acc.y += w * f01.y;
        acc.z += w * f23.x; acc.w += w * f23.y;
    }
    float inv = (e > s) ? 1.f / den : 0.f;
    __half2 p01 = __floats2half2_rn(acc.x * inv, acc.y * inv);
    __half2 p23 = __floats2half2_rn(acc.z * inv, acc.w * inv);
    *(uint2*)&g_A16[v * 128 + lane * 4] = make_uint2(*(uint32_t*)&p01, *(uint32_t*)&p23);
}

// ============ HMMA GEMM body: 64 rows x 128 cols, K=128, fp16 in ============
#define SM16_BIAS 0
#define SM16_X    512
#define SM16_TOTAL (SM16_X + 64 * 272)   // 17920 bytes

template <int MODE>
__device__ __forceinline__ void gemm16_body(
    const __half* __restrict__ X, const uint4* __restrict__ bfrag,
    const float* __restrict__ bias, float* __restrict__ outF,
    __half* __restrict__ outH, int ldo, int e0)
{
    extern __shared__ __align__(16) char smem[];
    uint32_t sb = smem_u32(smem);
    int t = threadIdx.x, lane = t & 31, wid = t >> 5;
    float* sBias = (float*)(smem + SM16_BIAS);
    sBias[t] = bias[t];

    {
        int row = t >> 1, hf = t & 1;
        int gr = e0 + row;
        uint4* xd = (uint4*)(smem + SM16_X + row * 272 + hf * 128);
        if (gr < N_NODES) {
            const uint4* xp = (const uint4*)(X + (size_t)gr * 128 + hf * 64);
#pragma unroll
            for (int j = 0; j < 8; j++) xd[j] = xp[j];
        } else {
#pragma unroll
            for (int j = 0; j < 8; j++) xd[j] = make_uint4(0, 0, 0, 0);
        }
    }
    __syncthreads();

    // warp tile M=64 x N=32 (same B-dedup trick)
    int s = wid;
    int n0 = s * 32;
    float acc[4][4][4];
#pragma unroll
    for (int i = 0; i < 4; i++)
#pragma unroll
        for (int j = 0; j < 4; j++)
#pragma unroll
            for (int c = 0; c < 4; c++) acc[i][j][c] = 0.f;

    uint32_t aOffL = ((lane & 15) * A_STRIDE + (lane >> 4) * 8) * 2;
    uint32_t Ab = sb + SM16_X;
    const uint4* bf = bfrag + (s >> 1) * 1024 + lane;
    int qb = (s & 1) * 2;

#pragma unroll
    for (int k8 = 0; k8 < 8; k8++) {
        uint32_t kb = k8 * 32;
        uint4 b0 = bf[k8 * 128 + (qb + 0) * 32];
        uint4 b1 = bf[k8 * 128 + (qb + 1) * 32];
        uint32_t a[4][4];
#pragma unroll
        for (int ms = 0; ms < 4; ms++)
            ldsm_x4(a[ms], Ab + aOffL + (uint32_t)(ms * 16) * 272 + kb);
        const uint32_t* p0 = (const uint32_t*)&b0;
        const uint32_t* p1 = (const uint32_t*)&b1;
#pragma unroll
        for (int ms = 0; ms < 4; ms++) {
            mma_f16(acc[ms][0], a[ms], p0);
            mma_f16(acc[ms][1], a[ms], p0 + 2);
            mma_f16(acc[ms][2], a[ms], p1);
            mma_f16(acc[ms][3], a[ms], p1 + 2);
        }
    }

#pragma unroll
    for (int ms = 0; ms < 4; ms++) {
        int r1 = ms * 16 + (lane >> 2);
#pragma unroll
        for (int rr = 0; rr < 2; rr++) {
            int gr = e0 + r1 + rr * 8;
            if (gr >= N_NODES) continue;
#pragma unroll
            for (int ns = 0; ns < 4; ns++) {
                int col = n0 + ns * 8 + (lane & 3) * 2;
                float v0 = acc[ms][ns][rr * 2]     + sBias[col];
                float v1 = acc[ms][ns][rr * 2 + 1] + sBias[col + 1];
                if (MODE == 1) {
                    v0 = (v0 > 0.f) ? v0 : (expf(v0) - 1.f);
                    v1 = (v1 > 0.f) ? v1 : (expf(v1) - 1.f);
                    *(__half2*)(outH + (size_t)gr * 128 + col) = __floats2half2_rn(v0, v1);
                } else {
                    *(float2*)(outF + (size_t)gr * ldo + col) = make_float2(v0, v1);
                }
            }
        }
    }
}

// launch #6: C_v = elu(A @ W_msg + b_msg) in fp16
__global__ __launch_bounds__(128, 4) void cv16_kernel(const float* __restrict__ b_msg) {
    gemm16_body<1>(g_A16, g_WmsgFrag, b_msg, nullptr, g_cv16, 128, blockIdx.x * 64);
}

// launch #7: gi = cv @ Wih^T + b_ih ; gh = h_v @ Whh^T + b_hh (fp32 out)
__global__ __launch_bounds__(128, 4) void gru16_kernel(const float* __restrict__ b_ih,
                                                       const float* __restrict__ b_hh) {
    int mat = blockIdx.y / 3, chunk = blockIdx.y % 3;
    const __half* X = mat ? g_h_v16 : g_cv16;
    const uint4* bf = (mat ? g_WhhFrag : g_WihFrag) + chunk * 2048;
    const float* bias = (mat ? b_hh : b_ih) + chunk * 128;
    float* outp = (mat ? g_gh : g_gi) + chunk * 128;
    gemm16_body<0>(X, bf, bias, outp, nullptr, 384, blockIdx.x * 64);
}

// ---------------- launch #8: GRU gates + relu ----------------
__global__ void gate_kernel(float* __restrict__ out) {
    int idx = blockIdx.x * blockDim.x + threadIdx.x;
    if (idx >= N_NODES * NHID) return;
    int n = idx >> 7, j = idx & 127;
    const float* gi = &g_gi[n * 384];
    const float* gh = &g_gh[n * 384];
    float r = 1.f / (1.f + expf(-(gi[j] + gh[j])));
    float z = 1.f / (1.f + expf(-(gi[128 + j] + gh[128 + j])));
    float nn = tanhf(gi[256 + j] + r * gh[256 + j]);
    float hv = g_h_v[idx];
    float h = (1.f - z) * nn + z * hv;
    out[idx] = h > 0.f ? h : 0.f;
}

// ---------------- launch ----------------
extern "C" void kernel_launch(void* const* d_in, const int* in_sizes, int n_in,
                              void* d_out, int out_size) {
    const float* node_feats = (const float*)d_in[0];
    const float* edge_feats = (const float*)d_in[1];
    const float* W_node  = (const float*)d_in[2];
    const float* b_node  = (const float*)d_in[3];
    const float* W_edge  = (const float*)d_in[4];
    const float* b_edge  = (const float*)d_in[5];
    const float* W_logit = (const float*)d_in[6];
    const float* b_logit = (const float*)d_in[7];
    const float* W_msg   = (const float*)d_in[8];
    const float* b_msg   = (const float*)d_in[9];
    const float* W_ih    = (const float*)d_in[10];
    const float* W_hh    = (const float*)d_in[11];
    const float* b_ih    = (const float*)d_in[12];
    const float* b_hh    = (const float*)d_in[13];
    const int*   src     = (const int*)d_in[14];
    const int*   dst     = (const int*)d_in[15];
    float* out = (float*)d_out;

    int* p_cnt;
    __half* p_nf16;
    cudaGetSymbolAddress((void**)&p_cnt, g_cnt);
    cudaGetSymbolAddress((void**)&p_nf16, g_nf16);

    const int SM_NODE = (64 * 128 + 64 * 64 + 256) * 4;
    cudaFuncSetAttribute(edge_mma_kernel, cudaFuncAttributeMaxDynamicSharedMemorySize, SM_EDGE_TOTAL);
    cudaFuncSetAttribute(node_embed_kernel, cudaFuncAttributeMaxDynamicSharedMemorySize, SM_NODE);
    cudaFuncSetAttribute(cv16_kernel, cudaFuncAttributeMaxDynamicSharedMemorySize, SM16_TOTAL);
    cudaFuncSetAttribute(gru16_kernel, cudaFuncAttributeMaxDynamicSharedMemorySize, SM16_TOTAL);

    cudaMemsetAsync(p_cnt, 0, N_NODES * sizeof(int));

    // #1 histogram + nf16 + all fragment prep
    hist_prep_kernel<<<(N_EDGES + 255) / 256, 256>>>(dst, node_feats, W_edge, W_ih, W_hh, W_msg);
    // #2 scan (warp-shuffle)
    scan_kernel<<<1, 1024>>>();
    // #3 node embed + fused hvdot + fp16 copy
    int ntiles64 = (N_NODES + 63) / 64;
    node_embed_kernel<<<ntiles64, 256, SM_NODE>>>(node_feats, W_node, b_node, W_logit);
    // #4 edge GEMM on tensor cores (profiled slot)
    float* outEF = (out_size >= N_NODES * NHID + N_EDGES * 64) ? (out + N_NODES * NHID) : nullptr;
    edge_mma_kernel<<<N_EDGES / 64, 128, SM_EDGE_TOTAL>>>(p_nf16, edge_feats, src, dst,
                                                          b_edge, W_logit, b_logit, outEF);
    // #5 softmax-weighted segment sum -> A16
    aggregate_kernel<<<(N_NODES + 7) / 8, 256>>>();
    // #6 C_v (HMMA, fp16 out)
    cv16_kernel<<<ntiles64, 128, SM16_TOTAL>>>(b_msg);
    // #7 gi / gh (HMMA, fp32 out)
    gru16_kernel<<<dim3(ntiles64, 6), 128, SM16_TOTAL>>>(b_ih, b_hh);
    // #8 gates -> h_new
    gate_kernel<<<(N_NODES * NHID + 255) / 256, 256>>>(out);
}

// round 14
// speedup vs baseline: 1.1271x; 1.0578x over previous
#include <cuda_runtime.h>
#include <cuda_bf16.h>
#include <cuda_fp16.h>
#include <math.h>
#include <stdint.h>

#define N_NODES 10000
#define N_EDGES 640000
#define NHID    128
#define EHID    128
#define CSIZE   128

// ---------------- scratch (device globals; no allocation) ----------------
__device__ float g_h_v[N_NODES * NHID];
__device__ __half g_h_v16[N_NODES * NHID];
__device__ __half g_nf16[N_NODES * 64];
__device__ float g_hvdot[N_NODES];
__device__ __half g_h_e16[(size_t)N_EDGES * EHID];  // CSR-ordered rows, fp16 (164MB)
__device__ float g_logit[N_EDGES];                  // CSR-ordered
__device__ __half g_A16[N_NODES * EHID];
__device__ __half g_cv16[N_NODES * CSIZE];
__device__ float g_gi[N_NODES * 3 * NHID];
__device__ float g_gh[N_NODES * 3 * NHID];
__device__ int   g_cnt[N_NODES];
__device__ int   g_off[N_NODES + 1];
__device__ int   g_cur[N_NODES];
// fragment images: [ng(2)][k8(8)][q(4)][lane(32)] uint4 each (2048 entries / 128x128 matrix)
__device__ uint4 g_BfragE[2048];        // W_edge^T
__device__ uint4 g_WihFrag[3 * 2048];   // W_ih rows (B[n][k] = Wih[n][k])
__device__ uint4 g_WhhFrag[3 * 2048];
__device__ uint4 g_WmsgFrag[2048];      // W_msg^T

#define A_STRIDE 136   // halves; 272 bytes

__device__ __forceinline__ float leaky01(float v) { return v > 0.f ? v : 0.01f * v; }

__device__ __forceinline__ uint32_t smem_u32(const void* p) {
    uint32_t a;
    asm("{ .reg .u64 t; cvta.to.shared.u64 t, %1; cvt.u32.u64 %0, t; }" : "=r"(a) : "l"(p));
    return a;
}
__device__ __forceinline__ void ldsm_x4(uint32_t* r, uint32_t addr) {
    asm volatile("ldmatrix.sync.aligned.m8n8.x4.shared.b16 {%0,%1,%2,%3}, [%4];"
        : "=r"(r[0]), "=r"(r[1]), "=r"(r[2]), "=r"(r[3]) : "r"(addr));
}
__device__ __forceinline__ void mma_f16(float* c, const uint32_t* a, const uint32_t* b) {
    asm volatile("mma.sync.aligned.m16n8k16.row.col.f32.f16.f16.f32 "
        "{%0,%1,%2,%3}, {%4,%5,%6,%7}, {%8,%9}, {%0,%1,%2,%3};"
        : "+f"(c[0]), "+f"(c[1]), "+f"(c[2]), "+f"(c[3])
        : "r"(a[0]), "r"(a[1]), "r"(a[2]), "r"(a[3]), "r"(b[0]), "r"(b[1]));
}

// fragment builders for mma m16n8k16 .col B fragments
__device__ __forceinline__ uint4 frag_colmajor(const float* M, int f) {  // B[n][k] = M[k*128+n]
    int lane = f & 31, q = (f >> 5) & 3, k8 = (f >> 7) & 7, ng = f >> 10;
    int n1 = ng * 64 + q * 16 + (lane >> 2), n2 = n1 + 8;
    int k0 = k8 * 16 + 2 * (lane & 3);
    uint4 v; __half2 h;
    h = __floats2half2_rn(M[k0 * 128 + n1], M[(k0 + 1) * 128 + n1]); v.x = *(uint32_t*)&h;
    h = __floats2half2_rn(M[(k0 + 8) * 128 + n1], M[(k0 + 9) * 128 + n1]); v.y = *(uint32_t*)&h;
    h = __floats2half2_rn(M[k0 * 128 + n2], M[(k0 + 1) * 128 + n2]); v.z = *(uint32_t*)&h;
    h = __floats2half2_rn(M[(k0 + 8) * 128 + n2], M[(k0 + 9) * 128 + n2]); v.w = *(uint32_t*)&h;
    return v;
}
__device__ __forceinline__ uint4 frag_rowmajor(const float* M, int f, int nbase) { // B[n][k] = M[(nbase+n)*128+k]
    int lane = f & 31, q = (f >> 5) & 3, k8 = (f >> 7) & 7, ng = f >> 10;
    int n1 = nbase + ng * 64 + q * 16 + (lane >> 2), n2 = n1 + 8;
    int k0 = k8 * 16 + 2 * (lane & 3);
    uint4 v; __half2 h;
    h = __floats2half2_rn(M[n1 * 128 + k0], M[n1 * 128 + k0 + 1]); v.x = *(uint32_t*)&h;
    h = __floats2half2_rn(M[n1 * 128 + k0 + 8], M[n1 * 128 + k0 + 9]); v.y = *(uint32_t*)&h;
    h = __floats2half2_rn(M[n2 * 128 + k0], M[n2 * 128 + k0 + 1]); v.z = *(uint32_t*)&h;
    h = __floats2half2_rn(M[n2 * 128 + k0 + 8], M[n2 * 128 + k0 + 9]); v.w = *(uint32_t*)&h;
    return v;
}

// ---------------- launch #1: histogram + nf16 + all fragment-image prep ----------------
__global__ void hist_prep_kernel(const int* __restrict__ dst,
                                 const float* __restrict__ nf,
                                 const float* __restrict__ We,
                                 const float* __restrict__ Wih,
                                 const float* __restrict__ Whh,
                                 const float* __restrict__ Wmsg)
{
    int e = blockIdx.x * blockDim.x + threadIdx.x;
    if (e < N_EDGES) atomicAdd(&g_cnt[dst[e]], 1);
    if (e < N_NODES * 32) {
        float2 f = *(const float2*)&nf[e * 2];
        *(__half2*)&g_nf16[e * 2] = __floats2half2_rn(f.x, f.y);
    }
    if (e < 2048) {
        g_BfragE[e] = frag_colmajor(We, e);
    } else if (e < 2048 + 3 * 2048) {
        int idx = e - 2048;
        g_WihFrag[idx] = frag_rowmajor(Wih, idx & 2047, (idx >> 11) * 128);
    } else if (e < 2048 + 6 * 2048) {
        int idx = e - 2048 - 3 * 2048;
        g_WhhFrag[idx] = frag_rowmajor(Whh, idx & 2047, (idx >> 11) * 128);
    } else if (e < 2048 + 7 * 2048) {
        int idx = e - 2048 - 6 * 2048;
        g_WmsgFrag[idx] = frag_colmajor(Wmsg, idx);
    }
}

// ---------------- launch #2: exclusive scan (warp-shuffle) ----------------
__global__ void scan_kernel() {
    __shared__ int warpsum[32];
    __shared__ int s_carry;
    int t = threadIdx.x, lane = t & 31, w = t >> 5;
    if (t == 0) s_carry = 0;
    __syncthreads();
    for (int base = 0; base < N_NODES; base += 1024) {
        int i = base + t;
        int v = (i < N_NODES) ? g_cnt[i] : 0;
        int x = v;
#pragma unroll
        for (int d = 1; d < 32; d <<= 1) {
            int y = __shfl_up_sync(0xffffffffu, x, d);
            if (lane >= d) x += y;
        }
        if (lane == 31) warpsum[w] = x;
        __syncthreads();
        if (w == 0) {
            int s = warpsum[lane];
#pragma unroll
            for (int d = 1; d < 32; d <<= 1) {
                int y = __shfl_up_sync(0xffffffffu, s, d);
                if (lane >= d) s += y;
            }
            warpsum[lane] = s;
        }
        __syncthreads();
        int incl = x + (w ? warpsum[w - 1] : 0) + s_carry;
        if (i < N_NODES) { g_off[i] = incl - v; g_cur[i] = incl - v; }
        __syncthreads();
        if (t == 1023) s_carry = incl;
        __syncthreads();
    }
    if (t == 0) g_off[N_NODES] = s_carry;
}

// ---------------- launch #3: node embed GEMM (K=64, leaky) + fused hvdot + fp16 copy ----------------
__global__ __launch_bounds__(256) void node_embed_kernel(
    const float* __restrict__ nf, const float* __restrict__ Wn,
    const float* __restrict__ bn, const float* __restrict__ Wl)
{
    extern __shared__ float sm[];
    float* sW = sm;            // 64*128
    float* sX = sm + 8192;     // 64*64
    float* sB = sm + 12288;    // 128
    float* sWL = sm + 12416;   // 128
    int t = threadIdx.x;
    int r0g = blockIdx.x * 64;
    for (int i = t; i < 64 * 128; i += 256) {
        int k = i >> 7, c = i & 127;
        sW[i] = Wn[k * 128 + c];
    }
    for (int i = t; i < 64 * 64; i += 256) {
        int r = i >> 6, k = i & 63;
        int gr = r0g + r;
        sX[i] = (gr < N_NODES) ? nf[gr * 64 + k] : 0.f;
    }
    if (t < 128) { sB[t] = bn[t]; sWL[t] = Wl[t]; }
    __syncthreads();
    int cx = t & 31, cy = t >> 5;
    int r0 = cy * 8, c0 = cx * 4;
    float acc[8][4] = {};
#pragma unroll 4
    for (int k = 0; k < 64; k++) {
        float4 w = *(const float4*)&sW[k * 128 + c0];
#pragma unroll
        for (int r = 0; r < 8; r++) {
            float x = sX[(r0 + r) * 64 + k];
            acc[r][0] += x * w.x; acc[r][1] += x * w.y;
            acc[r][2] += x * w.z; acc[r][3] += x * w.w;
        }
    }
    float wl0 = sWL[c0], wl1 = sWL[c0 + 1], wl2 = sWL[c0 + 2], wl3 = sWL[c0 + 3];
#pragma unroll
    for (int r = 0; r < 8; r++) {
        int gr = r0g + r0 + r;
        if (gr >= N_NODES) break;
        float v0 = leaky01(acc[r][0] + sB[c0]);
        float v1 = leaky01(acc[r][1] + sB[c0 + 1]);
        float v2 = leaky01(acc[r][2] + sB[c0 + 2]);
        float v3 = leaky01(acc[r][3] + sB[c0 + 3]);
        *(float4*)&g_h_v[(size_t)gr * 128 + c0] = make_float4(v0, v1, v2, v3);
        __half2 p01 = __floats2half2_rn(v0, v1);
        __half2 p23 = __floats2half2_rn(v2, v3);
        *(uint2*)&g_h_v16[(size_t)gr * 128 + c0] = make_uint2(*(uint32_t*)&p01, *(uint32_t*)&p23);
        float p = v0 * wl0 + v1 * wl1 + v2 * wl2 + v3 * wl3;
        for (int o = 16; o; o >>= 1) p += __shfl_xor_sync(0xffffffffu, p, o);
        if (cx == 0) g_hvdot[gr] = p;
    }
}

// ============ launch #4: edge GEMM on HMMA, warp tile M=64 x N=32 (B read once/CTA) ============
#define SM_SRC   0
#define SM_PERM  256
#define SM_BIAS  512
#define SM_WL    1024
#define SM_LOG   1536     // 256 floats (64 rows x 4 slices)
#define SM_A     2560
#define SM_EDGE_TOTAL (SM_A + 64 * 272)   // 19968 bytes -> 4 CTAs/SM

__global__ __launch_bounds__(128, 4)
void edge_mma_kernel(const __half* __restrict__ nf16, const float* __restrict__ ef,
                     const int* __restrict__ src, const int* __restrict__ dst,
                     const float* __restrict__ b_edge,
                     const float* __restrict__ W_logit, const float* __restrict__ b_logit,
                     float* __restrict__ outEF)
{
    extern __shared__ __align__(16) char smem[];
    uint32_t sb = smem_u32(smem);
    int t = threadIdx.x, lane = t & 31, wid = t >> 5;
    int e0 = blockIdx.x * 64;
    int* sSrc = (int*)(smem + SM_SRC);
    int* sPerm = (int*)(smem + SM_PERM);
    float* sBias = (float*)(smem + SM_BIAS);
    float* sWL = (float*)(smem + SM_WL);
    float* sLog = (float*)(smem + SM_LOG);

    if (t < 64) {
        sSrc[t] = src[e0 + t];
        sPerm[t] = atomicAdd(&g_cur[dst[e0 + t]], 1);
    }
    sBias[t] = b_edge[t];
    sWL[t] = W_logit[128 + t];
    __syncthreads();

    // ef: single read; passthrough copy + fp16 into A tile (concat cols 64..127)
    {
        const float4* efs = (const float4*)(ef + (size_t)e0 * 64);
        float4* efd = outEF ? (float4*)(outEF + (size_t)e0 * 64) : nullptr;
#pragma unroll
        for (int it = 0; it < 8; it++) {
            int i = t + it * 128;
            float4 v = efs[i];
            if (efd) efd[i] = v;
            int row = i >> 4, j = i & 15;
            __half2 h01 = __floats2half2_rn(v.x, v.y);
            __half2 h23 = __floats2half2_rn(v.z, v.w);
            *(uint2*)(smem + SM_A + row * 272 + 128 + j * 8)
                = make_uint2(*(uint32_t*)&h01, *(uint32_t*)&h23);
        }
    }
    // nf gather: fp16 rows straight into A tile (concat cols 0..63)
    {
        int r = t >> 1, hf = t & 1;
        const uint4* xp = (const uint4*)(nf16 + (size_t)sSrc[r] * 64 + hf * 32);
        uint4* xd = (uint4*)(smem + SM_A + r * 272 + hf * 64);
#pragma unroll
        for (int j = 0; j < 4; j++) xd[j] = xp[j];
    }
    __syncthreads();

    // warp tile: 4 warps, each M=64 (all rows) x N=32 (slice s = wid)
    int s = wid;
    int n0 = s * 32;
    float acc[4][4][4];
#pragma unroll
    for (int i = 0; i < 4; i++)
#pragma unroll
        for (int j = 0; j < 4; j++)
#pragma unroll
            for (int c = 0; c < 4; c++) acc[i][j][c] = 0.f;

    uint32_t aOffL = ((lane & 15) * A_STRIDE + (lane >> 4) * 8) * 2;
    uint32_t Ab = sb + SM_A;
    const uint4* bf = g_BfragE + (s >> 1) * 1024 + lane;
    int qb = (s & 1) * 2;

#pragma unroll
    for (int k8 = 0; k8 < 8; k8++) {
        uint32_t kb = k8 * 32;
        uint4 b0 = bf[k8 * 128 + (qb + 0) * 32];
        uint4 b1 = bf[k8 * 128 + (qb + 1) * 32];
        uint32_t a[4][4];
#pragma unroll
        for (int ms = 0; ms < 4; ms++)
            ldsm_x4(a[ms], Ab + aOffL + (uint32_t)(ms * 16) * 272 + kb);
        const uint32_t* p0 = (const uint32_t*)&b0;
        const uint32_t* p1 = (const uint32_t*)&b1;
#pragma unroll
        for (int ms = 0; ms < 4; ms++) {
            mma_f16(acc[ms][0], a[ms], p0);
            mma_f16(acc[ms][1], a[ms], p0 + 2);
            mma_f16(acc[ms][2], a[ms], p1);
            mma_f16(acc[ms][3], a[ms], p1 + 2);
        }
    }
    __syncthreads();   // A tile reads done -> safe to reuse as h_e staging

    // epilogue: bias + leaky -> smem staging (272B-stride rows) + partial logit
#pragma unroll
    for (int ms = 0; ms < 4; ms++) {
        int r1 = ms * 16 + (lane >> 2);
        int r2 = r1 + 8;
        float lg1 = 0.f, lg2 = 0.f;
#pragma unroll
        for (int ns = 0; ns < 4; ns++) {
            int col = n0 + ns * 8 + (lane & 3) * 2;
            float v0 = leaky01(acc[ms][ns][0] + sBias[col]);
            float v1 = leaky01(acc[ms][ns][1] + sBias[col + 1]);
            float v2 = leaky01(acc[ms][ns][2] + sBias[col]);
            float v3 = leaky01(acc[ms][ns][3] + sBias[col + 1]);
            lg1 += v0 * sWL[col] + v1 * sWL[col + 1];
            lg2 += v2 * sWL[col] + v3 * sWL[col + 1];
            *(__half2*)(smem + SM_A + r1 * 272 + col * 2) = __floats2half2_rn(v0, v1);
            *(__half2*)(smem + SM_A + r2 * 272 + col * 2) = __floats2half2_rn(v2, v3);
        }
        lg1 += __shfl_xor_sync(0xffffffffu, lg1, 1);
        lg1 += __shfl_xor_sync(0xffffffffu, lg1, 2);
        lg2 += __shfl_xor_sync(0xffffffffu, lg2, 1);
        lg2 += __shfl_xor_sync(0xffffffffu, lg2, 2);
        if ((lane & 3) == 0) {
            sLog[r1 * 4 + s] = lg1;
            sLog[r2 * 4 + s] = lg2;
        }
    }
    __syncthreads();

    // coalesced h_e writeout: 2 threads/row, 128B each
    {
        int r = t >> 1, hf = t & 1;
        const uint4* sp = (const uint4*)(smem + SM_A + r * 272 + hf * 128);
        uint4* dp = (uint4*)(g_h_e16 + (size_t)sPerm[r] * 128 + hf * 64);
#pragma unroll
        for (int j = 0; j < 8; j++) dp[j] = sp[j];
    }
    if (t < 64) {
        float sum = sLog[t * 4] + sLog[t * 4 + 1] + sLog[t * 4 + 2] + sLog[t * 4 + 3]
                  + g_hvdot[sSrc[t]] + b_logit[0];
        g_logit[sPerm[t]] = leaky01(sum);
    }
}

// ---------------- launch #5: per-node softmax + weighted sum -> A (fp16), 4x unrolled ----------------
__global__ void aggregate_kernel() {
    int v = (blockIdx.x * blockDim.x + threadIdx.x) >> 5;
    int lane = threadIdx.x & 31;
    if (v >= N_NODES) return;
    int s = g_off[v], e = g_off[v + 1];
    float mx = -1e30f;
    for (int i = s + lane; i < e; i += 32)
        mx = fmaxf(mx, g_logit[i]);
    for (int o = 16; o; o >>= 1)
        mx = fmaxf(mx, __shfl_xor_sync(0xffffffffu, mx, o));

    float4 accA = make_float4(0.f, 0.f, 0.f, 0.f);
    float4 accB = make_float4(0.f, 0.f, 0.f, 0.f);
    float denA = 0.f, denB = 0.f;
    const __half* hb = g_h_e16 + (size_t)lane * 4;
    int i = s;
    for (; i + 4 <= e; i += 4) {
        // issue all loads first (MLP=4 rows + 4 logits)
        float l0 = g_logit[i], l1 = g_logit[i + 1];
        float l2 = g_logit[i + 2], l3 = g_logit[i + 3];
        uint2 r0 = *(const uint2*)(hb + (size_t)i * 128);
        uint2 r1 = *(const uint2*)(hb + (size_t)(i + 1) * 128);
        uint2 r2 = *(const uint2*)(hb + (size_t)(i + 2) * 128);
        uint2 r3 = *(const uint2*)(hb + (size_t)(i + 3) * 128);
        float w0 = __expf(l0 - mx), w1 = __expf(l1 - mx);
        float w2 = __expf(l2 - mx), w3 = __expf(l3 - mx);
        denA += w0 + w2; denB += w1 + w3;
        float2 a0 = __half22float2(*(__half2*)&r0.x), b0 = __half22float2(*(__half2*)&r0.y);
        float2 a1 = __half22float2(*(__half2*)&r1.x), b1 = __half22float2(*(__half2*)&r1.y);
        float2 a2 = __half22float2(*(__half2*)&r2.x), b2 = __half22float2(*(__half2*)&r2.y);
        float2 a3 = __half22float2(*(__half2*)&r3.x), b3 = __half22float2(*(__half2*)&r3.y);
        accA.x += w0 * a0.x + w2 * a2.x;  accB.x += w1 * a1.x + w3 * a3.x;
        accA.y += w0 * a0.y + w2 * a2.y;  accB.y += w1 * a1.y + w3 * a3.y;
        accA.z += w0 * b0.x + w2 * b2.x;  accB.z += w1 * b1.x + w3 * b3.x;
        accA.w += w0 * b0.y + w2 * b2.y;  accB.w += w1 * b1.y + w3 * b3.y;
    }
    for (; i < e; i++) {
        float w = __expf(g_logit[i] - mx);
        uint2 raw = *(const uint2*)(hb + (size_t)i * 128);
        float2 f01 = __half22float2(*(__half2*)&raw.x);
        float2 f23 = __half22float2(*(__half2*)&raw.y);
        denA += w;
        accA.x += w * f01.x; accA.y += w * f01.y;
        accA.z += w * f23.x; accA.w += w * f23.y;
    }
    float den = denA + denB;
    float inv = (e > s) ? 1.f / den : 0.f;
    __half2 p01 = __floats2half2_rn((accA.x + accB.x) * inv, (accA.y + accB.y) * inv);
    __half2 p23 = __floats2half2_rn((accA.z + accB.z) * inv, (accA.w + accB.w) * inv);
    *(uint2*)&g_A16[v * 128 + lane * 4] = make_uint2(*(uint32_t*)&p01, *(uint32_t*)&p23);
}

// ============ HMMA GEMM body: 64 rows x 128 cols, K=128, fp16 in ============
#define SM16_BIAS 0
#define SM16_X    512
#define SM16_TOTAL (SM16_X + 64 * 272)   // 17920 bytes

template <int MODE>
__device__ __forceinline__ void gemm16_body(
    const __half* __restrict__ X, const uint4* __restrict__ bfrag,
    const float* __restrict__ bias, float* __restrict__ outF,
    __half* __restrict__ outH, int ldo, int e0)
{
    extern __shared__ __align__(16) char smem[];
    uint32_t sb = smem_u32(smem);
    int t = threadIdx.x, lane = t & 31, wid = t >> 5;
    float* sBias = (float*)(smem + SM16_BIAS);
    sBias[t] = bias[t];

    {
        int row = t >> 1, hf = t & 1;
        int gr = e0 + row;
        uint4* xd = (uint4*)(smem + SM16_X + row * 272 + hf * 128);
        if (gr < N_NODES) {
            const uint4* xp = (const uint4*)(X + (size_t)gr * 128 + hf * 64);
#pragma unroll
            for (int j = 0; j < 8; j++) xd[j] = xp[j];
        } else {
#pragma unroll
            for (int j = 0; j < 8; j++) xd[j] = make_uint4(0, 0, 0, 0);
        }
    }
    __syncthreads();

    // warp tile M=64 x N=32 (B-dedup)
    int s = wid;
    int n0 = s * 32;
    float acc[4][4][4];
#pragma unroll
    for (int i = 0; i < 4; i++)
#pragma unroll
        for (int j = 0; j < 4; j++)
#pragma unroll
            for (int c = 0; c < 4; c++) acc[i][j][c] = 0.f;

    uint32_t aOffL = ((lane & 15) * A_STRIDE + (lane >> 4) * 8) * 2;
    uint32_t Ab = sb + SM16_X;
    const uint4* bf = bfrag + (s >> 1) * 1024 + lane;
    int qb = (s & 1) * 2;

#pragma unroll
    for (int k8 = 0; k8 < 8; k8++) {
        uint32_t kb = k8 * 32;
        uint4 b0 = bf[k8 * 128 + (qb + 0) * 32];
        uint4 b1 = bf[k8 * 128 + (qb + 1) * 32];
        uint32_t a[4][4];
#pragma unroll
        for (int ms = 0; ms < 4; ms++)
            ldsm_x4(a[ms], Ab + aOffL + (uint32_t)(ms * 16) * 272 + kb);
        const uint32_t* p0 = (const uint32_t*)&b0;
        const uint32_t* p1 = (const uint32_t*)&b1;
#pragma unroll
        for (int ms = 0; ms < 4; ms++) {
            mma_f16(acc[ms][0], a[ms], p0);
            mma_f16(acc[ms][1], a[ms], p0 + 2);
            mma_f16(acc[ms][2], a[ms], p1);
            mma_f16(acc[ms][3], a[ms], p1 + 2);
        }
    }

#pragma unroll
    for (int ms = 0; ms < 4; ms++) {
        int r1 = ms * 16 + (lane >> 2);
#pragma unroll
        for (int rr = 0; rr < 2; rr++) {
            int gr = e0 + r1 + rr * 8;
            if (gr >= N_NODES) continue;
#pragma unroll
            for (int ns = 0; ns < 4; ns++) {
                int col = n0 + ns * 8 + (lane & 3) * 2;
                float v0 = acc[ms][ns][rr * 2]     + sBias[col];
                float v1 = acc[ms][ns][rr * 2 + 1] + sBias[col + 1];
                if (MODE == 1) {
                    v0 = (v0 > 0.f) ? v0 : (__expf(v0) - 1.f);
                    v1 = (v1 > 0.f) ? v1 : (__expf(v1) - 1.f);
                    *(__half2*)(outH + (size_t)gr * 128 + col) = __floats2half2_rn(v0, v1);
                } else {
                    *(float2*)(outF + (size_t)gr * ldo + col) = make_float2(v0, v1);
                }
            }
        }
    }
}

// launch #6: C_v = elu(A @ W_msg + b_msg) in fp16
__global__ __launch_bounds__(128, 4) void cv16_kernel(const float* __restrict__ b_msg) {
    gemm16_body<1>(g_A16, g_WmsgFrag, b_msg, nullptr, g_cv16, 128, blockIdx.x * 64);
}

// launch #7: gi = cv @ Wih^T + b_ih ; gh = h_v @ Whh^T + b_hh (fp32 out)
__global__ __launch_bounds__(128, 4) void gru16_kernel(const float* __restrict__ b_ih,
                                                       const float* __restrict__ b_hh) {
    int mat = blockIdx.y / 3, chunk = blockIdx.y % 3;
    const __half* X = mat ? g_h_v16 : g_cv16;
    const uint4* bf = (mat ? g_WhhFrag : g_WihFrag) + chunk * 2048;
    const float* bias = (mat ? b_hh : b_ih) + chunk * 128;
    float* outp = (mat ? g_gh : g_gi) + chunk * 128;
    gemm16_body<0>(X, bf, bias, outp, nullptr, 384, blockIdx.x * 64);
}

// ---------------- launch #8: GRU gates + relu ----------------
__global__ void gate_kernel(float* __restrict__ out) {
    int idx = blockIdx.x * blockDim.x + threadIdx.x;
    if (idx >= N_NODES * NHID) return;
    int n = idx >> 7, j = idx & 127;
    const float* gi = &g_gi[n * 384];
    const float* gh = &g_gh[n * 384];
    float r = 1.f / (1.f + __expf(-(gi[j] + gh[j])));
    float z = 1.f / (1.f + __expf(-(gi[128 + j] + gh[128 + j])));
    float nn = tanhf(gi[256 + j] + r * gh[256 + j]);
    float hv = g_h_v[idx];
    float h = (1.f - z) * nn + z * hv;
    out[idx] = h > 0.f ? h : 0.f;
}

// ---------------- launch ----------------
extern "C" void kernel_launch(void* const* d_in, const int* in_sizes, int n_in,
                              void* d_out, int out_size) {
    const float* node_feats = (const float*)d_in[0];
    const float* edge_feats = (const float*)d_in[1];
    const float* W_node  = (const float*)d_in[2];
    const float* b_node  = (const float*)d_in[3];
    const float* W_edge  = (const float*)d_in[4];
    const float* b_edge  = (const float*)d_in[5];
    const float* W_logit = (const float*)d_in[6];
    const float* b_logit = (const float*)d_in[7];
    const float* W_msg   = (const float*)d_in[8];
    const float* b_msg   = (const float*)d_in[9];
    const float* W_ih    = (const float*)d_in[10];
    const float* W_hh    = (const float*)d_in[11];
    const float* b_ih    = (const float*)d_in[12];
    const float* b_hh    = (const float*)d_in[13];
    const int*   src     = (const int*)d_in[14];
    const int*   dst     = (const int*)d_in[15];
    float* out = (float*)d_out;

    int* p_cnt;
    __half* p_nf16;
    cudaGetSymbolAddress((void**)&p_cnt, g_cnt);
    cudaGetSymbolAddress((void**)&p_nf16, g_nf16);

    const int SM_NODE = (64 * 128 + 64 * 64 + 256) * 4;
    cudaFuncSetAttribute(edge_mma_kernel, cudaFuncAttributeMaxDynamicSharedMemorySize, SM_EDGE_TOTAL);
    cudaFuncSetAttribute(node_embed_kernel, cudaFuncAttributeMaxDynamicSharedMemorySize, SM_NODE);
    cudaFuncSetAttribute(cv16_kernel, cudaFuncAttributeMaxDynamicSharedMemorySize, SM16_TOTAL);
    cudaFuncSetAttribute(gru16_kernel, cudaFuncAttributeMaxDynamicSharedMemorySize, SM16_TOTAL);

    cudaMemsetAsync(p_cnt, 0, N_NODES * sizeof(int));

    // #1 histogram + nf16 + all fragment prep
    hist_prep_kernel<<<(N_EDGES + 255) / 256, 256>>>(dst, node_feats, W_edge, W_ih, W_hh, W_msg);
    // #2 scan (warp-shuffle)
    scan_kernel<<<1, 1024>>>();
    // #3 node embed + fused hvdot + fp16 copy
    int ntiles64 = (N_NODES + 63) / 64;
    node_embed_kernel<<<ntiles64, 256, SM_NODE>>>(node_feats, W_node, b_node, W_logit);
    // #4 edge GEMM on tensor cores (profiled slot)
    float* outEF = (out_size >= N_NODES * NHID + N_EDGES * 64) ? (out + N_NODES * NHID) : nullptr;
    edge_mma_kernel<<<N_EDGES / 64, 128, SM_EDGE_TOTAL>>>(p_nf16, edge_feats, src, dst,
                                                          b_edge, W_logit, b_logit, outEF);
    // #5 softmax-weighted segment sum -> A16 (4x unrolled)
    aggregate_kernel<<<(N_NODES + 7) / 8, 256>>>();
    // #6 C_v (HMMA, fp16 out)
    cv16_kernel<<<ntiles64, 128, SM16_TOTAL>>>(b_msg);
    // #7 gi / gh (HMMA, fp32 out)
    gru16_kernel<<<dim3(ntiles64, 6), 128, SM16_TOTAL>>>(b_ih, b_hh);
    // #8 gates -> h_new
    gate_kernel<<<(N_NODES * NHID + 255) / 256, 256>>>(out);
}